// round 1
// baseline (speedup 1.0000x reference)
#include <cuda_runtime.h>

#define NB 8
#define NN 256
#define BN (NB*NN)          // 2048 nodes
#define HD 64
#define NL 4
#define CRANGE 3.75f        // 15.0 / 4 layers

// ---------------- device scratch (no allocations allowed) ----------------
__device__ float g_h[BN*HD];
__device__ float g_H1A[BN*HD];
__device__ float g_H1B[BN*HD];
__device__ float g_Agg[BN*HD];
__device__ float g_coordA[BN*3];
__device__ float g_coordB[BN*3];
__device__ float g_x0[BN*3];

__device__ __forceinline__ float siluf(float x) { return x / (1.f + __expf(-x)); }
__device__ __forceinline__ float sigmf(float x) { return 1.f / (1.f + __expf(-x)); }

// ---------------- init: x0, coord, embedding ----------------
__global__ void k_init(const float* __restrict__ t, const float* __restrict__ x,
                       const float* __restrict__ at, const float* __restrict__ aat,
                       const float* __restrict__ aap, const float* __restrict__ nm,
                       const float* __restrict__ emb_w, const float* __restrict__ emb_b) {
    int bn = blockIdx.x;
    int b = bn >> 8, i = bn & 255;
    int k = threadIdx.x;                     // 64 threads
    float nmv = nm[bn];
    if (k < 3) {
        float v = x[b * (NN * 3) + i * 3 + k] * nmv;
        g_x0[bn * 3 + k] = v;
        g_coordA[bn * 3 + k] = v;
    }
    float f0 = at[bn] * nmv, f1 = aat[bn] * nmv, f2 = aap[bn] * nmv, f3 = t[b] * nmv;
    float h = emb_b[k] + emb_w[k * 4 + 0] * f0 + emb_w[k * 4 + 1] * f1
            + emb_w[k * 4 + 2] * f2 + emb_w[k * 4 + 3] * f3;
    g_h[bn * HD + k] = h;
}

// ---------------- per-layer node precompute: H1A, H1B ----------------
__global__ void k_nodepre(int l, const float* __restrict__ ew1, const float* __restrict__ eb1) {
    int bn = blockIdx.x;
    int k = threadIdx.x;                     // 64 threads
    __shared__ float sh[HD];
    __shared__ float sw[HD * 130];
    sh[k] = g_h[bn * HD + k];
    const float* wsrc = ew1 + (size_t)l * HD * 130;
    for (int idx = k; idx < HD * 130; idx += HD) sw[idx] = wsrc[idx];
    __syncthreads();
    const float* wr = sw + k * 130;
    float a = eb1[l * HD + k], bs = 0.f;
#pragma unroll 8
    for (int c = 0; c < HD; c++) {
        a  += wr[c] * sh[c];
        bs += wr[64 + c] * sh[c];
    }
    g_H1A[bn * HD + k] = a;
    g_H1B[bn * HD + k] = bs;
}

// ---------------- edge kernel: one CTA per target node (b,i) ----------------
// smem layout (floats)
#define S_W2    0
#define S_C1    4160
#define S_MS    8320
#define S_M2    12480
#define S_COORD 16640
#define S_X0    17408
#define S_NM    18176
#define S_H1A   18432
#define S_WR    18496
#define S_WE    18560
#define S_B2    18624
#define S_CB1   18688
#define S_AW    18752
#define S_CW2   18816
#define S_RAD   18880
#define S_E0    18944
#define S_ATTS  19008
#define S_DIFFN 19072
#define S_RED   19264
#define SMEM_FLOATS 19328
#define SMEM_BYTES  (SMEM_FLOATS * 4)

__global__ void __launch_bounds__(256, 2)
k_edge(int l, int ping,
       const float* __restrict__ ew1, const float* __restrict__ ew2,
       const float* __restrict__ eb2, const float* __restrict__ cw1,
       const float* __restrict__ cb1, const float* __restrict__ aw,
       const float* __restrict__ ab,  const float* __restrict__ cw2,
       const float* __restrict__ nm) {
    extern __shared__ float sm[];
    const float* cIn = ping ? g_coordB : g_coordA;
    float* cOut = ping ? g_coordA : g_coordB;

    int tid = threadIdx.x;
    int tx = tid & 15, ty = tid >> 4;
    int bn = blockIdx.x;
    int b = bn >> 8, i = bn & 255;

    // stage weights + per-graph state
    const float* w2g = ew2 + (size_t)l * 4096;
    const float* c1g = cw1 + (size_t)l * 4096;
    for (int e = tid; e < 4096; e += 256) {
        int kk = e >> 6, c = e & 63;
        sm[S_W2 + kk * 65 + c] = w2g[e];
        sm[S_C1 + kk * 65 + c] = c1g[e];
    }
    if (tid < 64) {
        sm[S_WR  + tid] = ew1[((size_t)l * 64 + tid) * 130 + 128];
        sm[S_WE  + tid] = ew1[((size_t)l * 64 + tid) * 130 + 129];
        sm[S_B2  + tid] = eb2[l * 64 + tid];
        sm[S_CB1 + tid] = cb1[l * 64 + tid];
        sm[S_AW  + tid] = aw[l * 64 + tid];
        sm[S_CW2 + tid] = cw2[l * 64 + tid];
        sm[S_H1A + tid] = g_H1A[bn * 64 + tid];
    }
    for (int e = tid; e < 768; e += 256) {
        sm[S_COORD + e] = cIn[b * 768 + e];
        sm[S_X0 + e] = g_x0[b * 768 + e];
    }
    sm[S_NM + tid] = (tid < 256) ? nm[b * 256 + tid] : 0.f;
    float attb = ab[l];
    float nmi = nm[bn];
    __syncthreads();

    float cix = sm[S_COORD + i * 3], ciy = sm[S_COORD + i * 3 + 1], ciz = sm[S_COORD + i * 3 + 2];
    float xix = sm[S_X0 + i * 3],    xiy = sm[S_X0 + i * 3 + 1],    xiz = sm[S_X0 + i * 3 + 2];

    float aggr = 0.f;                        // valid for tid<64 (channel tid)
    float cA0 = 0.f, cA1 = 0.f, cA2 = 0.f;   // valid for tx==0

    for (int tile = 0; tile < 4; tile++) {
        int j0 = tile * 64;
        // per-row geometry
        if (tid < 64) {
            int j = j0 + tid;
            float dx = cix - sm[S_COORD + j * 3];
            float dy = ciy - sm[S_COORD + j * 3 + 1];
            float dz = ciz - sm[S_COORD + j * 3 + 2];
            float rad = dx * dx + dy * dy + dz * dz;
            float inv = 1.f / (sqrtf(rad + 1e-8f) + 1.f);
            sm[S_RAD + tid] = rad;
            sm[S_DIFFN + tid * 3 + 0] = dx * inv;
            sm[S_DIFFN + tid * 3 + 1] = dy * inv;
            sm[S_DIFFN + tid * 3 + 2] = dz * inv;
            float ex = xix - sm[S_X0 + j * 3];
            float ey = xiy - sm[S_X0 + j * 3 + 1];
            float ez = xiz - sm[S_X0 + j * 3 + 2];
            sm[S_E0 + tid] = ex * ex + ey * ey + ez * ez;
        }
        __syncthreads();
        // Mpre + silu -> sMs
        const float* h1bg = g_H1B + ((size_t)(b * 256 + j0)) * 64;
        for (int e = tid; e < 4096; e += 256) {
            int jj = e >> 6, c = e & 63;
            float v = sm[S_H1A + c] + h1bg[e]
                    + sm[S_WR + c] * sm[S_RAD + jj] + sm[S_WE + c] * sm[S_E0 + jj];
            sm[S_MS + jj * 65 + c] = siluf(v);
        }
        __syncthreads();
        // GEMM1: sM2 = silu(sMs @ W2^T + b2)
        {
            float acc[4][4];
#pragma unroll
            for (int r = 0; r < 4; r++)
#pragma unroll
                for (int s = 0; s < 4; s++) acc[r][s] = sm[S_B2 + tx + 16 * s];
            const float* pa = sm + S_MS + ty * 65;
            const float* pw = sm + S_W2 + tx * 65;
#pragma unroll 4
            for (int c = 0; c < 64; c++) {
                float a0 = pa[c], a1 = pa[16 * 65 + c], a2 = pa[32 * 65 + c], a3 = pa[48 * 65 + c];
                float w0 = pw[c], w1 = pw[16 * 65 + c], w2 = pw[32 * 65 + c], w3 = pw[48 * 65 + c];
                acc[0][0] += a0 * w0; acc[0][1] += a0 * w1; acc[0][2] += a0 * w2; acc[0][3] += a0 * w3;
                acc[1][0] += a1 * w0; acc[1][1] += a1 * w1; acc[1][2] += a1 * w2; acc[1][3] += a1 * w3;
                acc[2][0] += a2 * w0; acc[2][1] += a2 * w1; acc[2][2] += a2 * w2; acc[2][3] += a2 * w3;
                acc[3][0] += a3 * w0; acc[3][1] += a3 * w1; acc[3][2] += a3 * w2; acc[3][3] += a3 * w3;
            }
#pragma unroll
            for (int r = 0; r < 4; r++)
#pragma unroll
                for (int s = 0; s < 4; s++)
                    sm[S_M2 + (ty + 16 * r) * 65 + tx + 16 * s] = siluf(acc[r][s]);
        }
        __syncthreads();
        // attention + mask per row
        if (tid < 64) {
            float dot = attb;
            const float* row = sm + S_M2 + tid * 65;
#pragma unroll 8
            for (int c = 0; c < 64; c++) dot += row[c] * sm[S_AW + c];
            int j = j0 + tid;
            float em = (j == i) ? 0.f : nmi * sm[S_NM + j];
            sm[S_ATTS + tid] = sigmf(dot) * em;
        }
        __syncthreads();
        for (int e = tid; e < 4096; e += 256) {
            int jj = e >> 6;
            sm[S_M2 + jj * 65 + (e & 63)] *= sm[S_ATTS + jj];
        }
        __syncthreads();
        // agg accumulate (channel = tid)
        if (tid < 64) {
            float s = aggr;
#pragma unroll 8
            for (int jj = 0; jj < 64; jj++) s += sm[S_M2 + jj * 65 + tid];
            aggr = s;
        }
        // GEMM2 + phi + trans
        {
            float acc[4][4];
#pragma unroll
            for (int r = 0; r < 4; r++)
#pragma unroll
                for (int s = 0; s < 4; s++) acc[r][s] = sm[S_CB1 + tx + 16 * s];
            const float* pa = sm + S_M2 + ty * 65;
            const float* pw = sm + S_C1 + tx * 65;
#pragma unroll 4
            for (int c = 0; c < 64; c++) {
                float a0 = pa[c], a1 = pa[16 * 65 + c], a2 = pa[32 * 65 + c], a3 = pa[48 * 65 + c];
                float w0 = pw[c], w1 = pw[16 * 65 + c], w2 = pw[32 * 65 + c], w3 = pw[48 * 65 + c];
                acc[0][0] += a0 * w0; acc[0][1] += a0 * w1; acc[0][2] += a0 * w2; acc[0][3] += a0 * w3;
                acc[1][0] += a1 * w0; acc[1][1] += a1 * w1; acc[1][2] += a1 * w2; acc[1][3] += a1 * w3;
                acc[2][0] += a2 * w0; acc[2][1] += a2 * w1; acc[2][2] += a2 * w2; acc[2][3] += a2 * w3;
                acc[3][0] += a3 * w0; acc[3][1] += a3 * w1; acc[3][2] += a3 * w2; acc[3][3] += a3 * w3;
            }
#pragma unroll
            for (int r = 0; r < 4; r++) {
                float p = 0.f;
#pragma unroll
                for (int s = 0; s < 4; s++) p += siluf(acc[r][s]) * sm[S_CW2 + tx + 16 * s];
                p += __shfl_xor_sync(0xffffffffu, p, 1);
                p += __shfl_xor_sync(0xffffffffu, p, 2);
                p += __shfl_xor_sync(0xffffffffu, p, 4);
                p += __shfl_xor_sync(0xffffffffu, p, 8);
                if (tx == 0) {
                    int jj = ty + 16 * r;
                    int j = j0 + jj;
                    float em = (j == i) ? 0.f : nmi * sm[S_NM + j];
                    float ph = tanhf(p) * CRANGE * em;
                    cA0 += sm[S_DIFFN + jj * 3 + 0] * ph;
                    cA1 += sm[S_DIFFN + jj * 3 + 1] * ph;
                    cA2 += sm[S_DIFFN + jj * 3 + 2] * ph;
                }
            }
        }
        __syncthreads();   // before next tile overwrites sMs/sM2/sRad/sDiffn
    }

    // epilogue
    if (tid < 64) g_Agg[bn * 64 + tid] = aggr;
    if (tx == 0) {
        sm[S_RED + ty * 3 + 0] = cA0;
        sm[S_RED + ty * 3 + 1] = cA1;
        sm[S_RED + ty * 3 + 2] = cA2;
    }
    __syncthreads();
    if (tid < 3) {
        float s = 0.f;
#pragma unroll
        for (int q = 0; q < 16; q++) s += sm[S_RED + q * 3 + tid];
        cOut[bn * 3 + tid] = (sm[S_COORD + i * 3 + tid] + s) * nmi;
    }
}

// ---------------- per-layer node update ----------------
__global__ void k_nodeupd(int l, const float* __restrict__ nw1, const float* __restrict__ nb1,
                          const float* __restrict__ nw2, const float* __restrict__ nb2,
                          const float* __restrict__ nm) {
    int bn = blockIdx.x;
    int k = threadIdx.x;                     // 64 threads
    __shared__ float sh[64], sa[64], st[64];
    sh[k] = g_h[bn * 64 + k];
    sa[k] = g_Agg[bn * 64 + k];
    __syncthreads();
    const float* w1 = nw1 + ((size_t)l * 64 + k) * 128;
    float acc = nb1[l * 64 + k];
#pragma unroll 8
    for (int c = 0; c < 64; c++) acc += w1[c] * sh[c] + w1[64 + c] * sa[c];
    st[k] = siluf(acc);
    __syncthreads();
    const float* w2 = nw2 + ((size_t)l * 64 + k) * 64;
    float u = nb2[l * 64 + k];
#pragma unroll 8
    for (int c = 0; c < 64; c++) u += w2[c] * st[c];
    g_h[bn * 64 + k] = (sh[k] + u) * nm[bn];
}

// ---------------- final: vel + remove mean ----------------
__global__ void k_final(const float* __restrict__ nm, float* __restrict__ out) {
    int b = blockIdx.x;
    int j = threadIdx.x;                     // 256 threads
    __shared__ float rs[256 * 4];
    int bn = b * 256 + j;
    float nmv = nm[bn];
    float v0 = (g_coordA[bn * 3 + 0] - g_x0[bn * 3 + 0]) * nmv;
    float v1 = (g_coordA[bn * 3 + 1] - g_x0[bn * 3 + 1]) * nmv;
    float v2 = (g_coordA[bn * 3 + 2] - g_x0[bn * 3 + 2]) * nmv;
    rs[j] = v0; rs[256 + j] = v1; rs[512 + j] = v2; rs[768 + j] = nmv;
    __syncthreads();
    for (int o = 128; o > 0; o >>= 1) {
        if (j < o) {
            rs[j] += rs[j + o];
            rs[256 + j] += rs[256 + j + o];
            rs[512 + j] += rs[512 + j + o];
            rs[768 + j] += rs[768 + j + o];
        }
        __syncthreads();
    }
    float inv = 1.f / rs[768];
    float m0 = rs[0] * inv, m1 = rs[256] * inv, m2 = rs[512] * inv;
    out[b * 768 + j * 3 + 0] = v0 - m0 * nmv;
    out[b * 768 + j * 3 + 1] = v1 - m1 * nmv;
    out[b * 768 + j * 3 + 2] = v2 - m2 * nmv;
}

// ---------------- launch ----------------
extern "C" void kernel_launch(void* const* d_in, const int* in_sizes, int n_in,
                              void* d_out, int out_size) {
    (void)in_sizes; (void)n_in; (void)out_size;
    const float* t     = (const float*)d_in[0];
    const float* x     = (const float*)d_in[1];
    const float* at    = (const float*)d_in[2];
    const float* aat   = (const float*)d_in[3];
    const float* aap   = (const float*)d_in[4];
    const float* nm    = (const float*)d_in[5];
    const float* emb_w = (const float*)d_in[6];
    const float* emb_b = (const float*)d_in[7];
    const float* ew1   = (const float*)d_in[8];
    const float* eb1   = (const float*)d_in[9];
    const float* ew2   = (const float*)d_in[10];
    const float* eb2   = (const float*)d_in[11];
    const float* nw1   = (const float*)d_in[12];
    const float* nb1   = (const float*)d_in[13];
    const float* nw2   = (const float*)d_in[14];
    const float* nb2   = (const float*)d_in[15];
    const float* cw1   = (const float*)d_in[16];
    const float* cb1   = (const float*)d_in[17];
    const float* aw    = (const float*)d_in[18];
    const float* ab    = (const float*)d_in[19];
    const float* cw2   = (const float*)d_in[20];
    float* out = (float*)d_out;

    cudaFuncSetAttribute(k_edge, cudaFuncAttributeMaxDynamicSharedMemorySize, SMEM_BYTES);

    k_init<<<BN, 64>>>(t, x, at, aat, aap, nm, emb_w, emb_b);
    for (int l = 0; l < NL; l++) {
        k_nodepre<<<BN, 64>>>(l, ew1, eb1);
        k_edge<<<BN, 256, SMEM_BYTES>>>(l, l & 1, ew1, ew2, eb2, cw1, cb1, aw, ab, cw2, nm);
        k_nodeupd<<<BN, 64>>>(l, nw1, nb1, nw2, nb2, nm);
    }
    k_final<<<NB, 256>>>(nm, out);
}

// round 3
// speedup vs baseline: 1.0807x; 1.0807x over previous
#include <cuda_runtime.h>

#define NB 8
#define NN 256
#define BN (NB*NN)          // 2048 nodes
#define HD 64
#define NL 4
#define CRANGE 3.75f        // 15.0 / 4 layers

// ---------------- device scratch ----------------
__device__ float g_h[BN*HD];
__device__ float g_H1A[BN*HD];
__device__ float g_H1B[2][BN*HD];   // double-buffered: read cross-node, written per-layer
__device__ float g_coordA[BN*3];
__device__ float g_coordB[BN*3];
__device__ float g_x0[BN*3];

__device__ __forceinline__ float siluf(float x) { return x / (1.f + __expf(-x)); }
__device__ __forceinline__ float sigmf(float x) { return 1.f / (1.f + __expf(-x)); }

typedef unsigned long long ull;
__device__ __forceinline__ ull pk2(float x, float y) {
    ull r; asm("mov.b64 %0, {%1,%2};" : "=l"(r) : "f"(x), "f"(y)); return r;
}
__device__ __forceinline__ void fma2(ull& d, ull a, ull b) {
    asm("fma.rn.f32x2 %0, %1, %2, %0;" : "+l"(d) : "l"(a), "l"(b));
}
__device__ __forceinline__ float2 upk2(ull v) {
    float2 f; asm("mov.b64 {%0,%1}, %2;" : "=f"(f.x), "=f"(f.y) : "l"(v)); return f;
}

// ---------------- init: x0, coord, embedding, layer-0 H1A/H1B ----------------
__global__ void k_init(const float* __restrict__ t, const float* __restrict__ x,
                       const float* __restrict__ at, const float* __restrict__ aat,
                       const float* __restrict__ aap, const float* __restrict__ nm,
                       const float* __restrict__ emb_w, const float* __restrict__ emb_b,
                       const float* __restrict__ ew1, const float* __restrict__ eb1) {
    int bn = blockIdx.x;
    int b = bn >> 8, i = bn & 255;
    int tid = threadIdx.x;                   // 256 threads
    __shared__ float sh[HD];
    float nmv = nm[bn];
    if (tid < 3) {
        float v = x[b * (NN * 3) + i * 3 + tid] * nmv;
        g_x0[bn * 3 + tid] = v;
        g_coordA[bn * 3 + tid] = v;
    }
    if (tid < 64) {
        float f0 = at[bn] * nmv, f1 = aat[bn] * nmv, f2 = aap[bn] * nmv, f3 = t[b] * nmv;
        float h = emb_b[tid] + emb_w[tid * 4 + 0] * f0 + emb_w[tid * 4 + 1] * f1
                + emb_w[tid * 4 + 2] * f2 + emb_w[tid * 4 + 3] * f3;
        g_h[bn * HD + tid] = h;
        sh[tid] = h;
    }
    __syncthreads();
    int k = tid >> 2, q = tid & 3;
    const float* w1 = ew1 + (size_t)k * 130 + q * 16;     // layer 0
    const float* hp = sh + q * 16;
    float a = 0.f, bv = 0.f;
#pragma unroll
    for (int c = 0; c < 16; c++) { a += w1[c] * hp[c]; bv += w1[64 + c] * hp[c]; }
    a  += __shfl_xor_sync(0xffffffffu, a, 1);
    a  += __shfl_xor_sync(0xffffffffu, a, 2);
    bv += __shfl_xor_sync(0xffffffffu, bv, 1);
    bv += __shfl_xor_sync(0xffffffffu, bv, 2);
    if (q == 0) {
        g_H1A[bn * 64 + k] = a + eb1[k];
        g_H1B[0][bn * 64 + k] = bv;
    }
}

// ---------------- edge kernel smem layout (floats) ----------------
#define S_W2T   0
#define S_C1T   4096
#define S_MS    8192
#define S_M2    12352
#define S_COORD 16512
#define S_X0    17280
#define S_NM    18048
#define S_H1A   18304
#define S_WR    18368
#define S_WE    18432
#define S_B2    18496
#define S_CB1   18560
#define S_AW    18624
#define S_CW2   18688
#define S_RAD   18752
#define S_E0    18816
#define S_ATTS  18880
#define S_DIFFN 18944
#define S_RED   19136
#define SMEM_FLOATS 19200
#define SMEM_BYTES  (SMEM_FLOATS * 4)

__global__ void __launch_bounds__(256, 2)
k_edge(int l,
       const float* __restrict__ ew1, const float* __restrict__ eb1,
       const float* __restrict__ ew2, const float* __restrict__ eb2,
       const float* __restrict__ nw1, const float* __restrict__ nb1,
       const float* __restrict__ nw2, const float* __restrict__ nb2,
       const float* __restrict__ cw1, const float* __restrict__ cb1,
       const float* __restrict__ aw,  const float* __restrict__ ab,
       const float* __restrict__ cw2, const float* __restrict__ nm) {
    extern __shared__ float sm[];
    int ping = l & 1;
    const float* cIn = ping ? g_coordB : g_coordA;
    float* cOut = ping ? g_coordA : g_coordB;
    const float* h1bIn = g_H1B[ping];
    float* h1bOut = g_H1B[ping ^ 1];

    int tid = threadIdx.x;
    int tx = tid & 15, ty = tid >> 4;
    int bn = blockIdx.x;
    int b = bn >> 8, i = bn & 255;

    // stage weights row-major into temp (S_MS / S_M2), small vectors, coords
    const float* w2g = ew2 + (size_t)l * 4096;
    const float* c1g = cw1 + (size_t)l * 4096;
    for (int e = tid; e < 4096; e += 256) {
        int kk = e >> 6, c = e & 63;
        sm[S_MS + kk * 65 + c] = w2g[e];
        sm[S_M2 + kk * 65 + c] = c1g[e];
    }
    if (tid < 64) {
        sm[S_WR  + tid] = ew1[((size_t)l * 64 + tid) * 130 + 128];
        sm[S_WE  + tid] = ew1[((size_t)l * 64 + tid) * 130 + 129];
        sm[S_B2  + tid] = eb2[l * 64 + tid];
        sm[S_CB1 + tid] = cb1[l * 64 + tid];
        sm[S_AW  + tid] = aw[l * 64 + tid];
        sm[S_CW2 + tid] = cw2[l * 64 + tid];
        sm[S_H1A + tid] = g_H1A[bn * 64 + tid];
    }
    for (int e = tid; e < 768; e += 256) {
        sm[S_COORD + e] = cIn[b * 768 + e];
        sm[S_X0 + e] = g_x0[b * 768 + e];
    }
    sm[S_NM + tid] = nm[b * 256 + tid];
    float attb = ab[l];
    float nmi = nm[bn];
    __syncthreads();
    // transpose weights: W2T[c*64+k] = W2[k][c]
    for (int e = tid; e < 4096; e += 256) {
        int c = e >> 6, kk = e & 63;
        sm[S_W2T + c * 64 + kk] = sm[S_MS + kk * 65 + c];
        sm[S_C1T + c * 64 + kk] = sm[S_M2 + kk * 65 + c];
    }
    __syncthreads();

    float cix = sm[S_COORD + i * 3], ciy = sm[S_COORD + i * 3 + 1], ciz = sm[S_COORD + i * 3 + 2];
    float xix = sm[S_X0 + i * 3],    xiy = sm[S_X0 + i * 3 + 1],    xiz = sm[S_X0 + i * 3 + 2];

    float aggr = 0.f;                        // valid for tid<64
    float cA0 = 0.f, cA1 = 0.f, cA2 = 0.f;   // valid for tx==0

    const ulonglong2* pw2 = (const ulonglong2*)(sm + S_W2T) + tx;
    const ulonglong2* pc1 = (const ulonglong2*)(sm + S_C1T) + tx;

    for (int tile = 0; tile < 4; tile++) {
        int j0 = tile * 64;
        if (tid < 64) {
            int j = j0 + tid;
            float dx = cix - sm[S_COORD + j * 3];
            float dy = ciy - sm[S_COORD + j * 3 + 1];
            float dz = ciz - sm[S_COORD + j * 3 + 2];
            float rad = dx * dx + dy * dy + dz * dz;
            float inv = 1.f / (sqrtf(rad + 1e-8f) + 1.f);
            sm[S_RAD + tid] = rad;
            sm[S_DIFFN + tid * 3 + 0] = dx * inv;
            sm[S_DIFFN + tid * 3 + 1] = dy * inv;
            sm[S_DIFFN + tid * 3 + 2] = dz * inv;
            float ex = xix - sm[S_X0 + j * 3];
            float ey = xiy - sm[S_X0 + j * 3 + 1];
            float ez = xiz - sm[S_X0 + j * 3 + 2];
            sm[S_E0 + tid] = ex * ex + ey * ey + ez * ez;
        }
        __syncthreads();
        // Mpre + silu -> S_MS
        const float* h1bg = h1bIn + ((size_t)(b * 256 + j0)) * 64;
        for (int e = tid; e < 4096; e += 256) {
            int jj = e >> 6, c = e & 63;
            float v = sm[S_H1A + c] + h1bg[e]
                    + sm[S_WR + c] * sm[S_RAD + jj] + sm[S_WE + c] * sm[S_E0 + jj];
            sm[S_MS + jj * 65 + c] = siluf(v);
        }
        __syncthreads();
        // GEMM1: M2 = silu(Ms @ W2^T + b2)   rows ty+16r, cols 4tx+{0..3}
        {
            ull acc[4][2];
            ull b01 = pk2(sm[S_B2 + 4 * tx], sm[S_B2 + 4 * tx + 1]);
            ull b23 = pk2(sm[S_B2 + 4 * tx + 2], sm[S_B2 + 4 * tx + 3]);
#pragma unroll
            for (int r = 0; r < 4; r++) { acc[r][0] = b01; acc[r][1] = b23; }
            const float* pa = sm + S_MS + ty * 65;
#pragma unroll 4
            for (int c = 0; c < 64; c++) {
                ulonglong2 w = pw2[c * 16];
                ull A0 = pk2(pa[c], pa[c]);
                ull A1 = pk2(pa[c + 16 * 65], pa[c + 16 * 65]);
                ull A2 = pk2(pa[c + 32 * 65], pa[c + 32 * 65]);
                ull A3 = pk2(pa[c + 48 * 65], pa[c + 48 * 65]);
                fma2(acc[0][0], A0, w.x); fma2(acc[0][1], A0, w.y);
                fma2(acc[1][0], A1, w.x); fma2(acc[1][1], A1, w.y);
                fma2(acc[2][0], A2, w.x); fma2(acc[2][1], A2, w.y);
                fma2(acc[3][0], A3, w.x); fma2(acc[3][1], A3, w.y);
            }
#pragma unroll
            for (int r = 0; r < 4; r++) {
                float2 v0 = upk2(acc[r][0]), v1 = upk2(acc[r][1]);
                float* dst = sm + S_M2 + (ty + 16 * r) * 65 + 4 * tx;
                dst[0] = siluf(v0.x); dst[1] = siluf(v0.y);
                dst[2] = siluf(v1.x); dst[3] = siluf(v1.y);
            }
        }
        __syncthreads();
        // attention per row
        if (tid < 64) {
            float dot = attb;
            const float* row = sm + S_M2 + tid * 65;
#pragma unroll 8
            for (int c = 0; c < 64; c++) dot += row[c] * sm[S_AW + c];
            int j = j0 + tid;
            float em = (j == i) ? 0.f : nmi * sm[S_NM + j];
            sm[S_ATTS + tid] = sigmf(dot) * em;
        }
        __syncthreads();
        for (int e = tid; e < 4096; e += 256) {
            int jj = e >> 6;
            sm[S_M2 + jj * 65 + (e & 63)] *= sm[S_ATTS + jj];
        }
        __syncthreads();
        // agg accumulate (channel = tid)
        if (tid < 64) {
            float s = aggr;
#pragma unroll 8
            for (int jj = 0; jj < 64; jj++) s += sm[S_M2 + jj * 65 + tid];
            aggr = s;
        }
        // GEMM2 + phi + trans
        {
            ull acc[4][2];
            ull b01 = pk2(sm[S_CB1 + 4 * tx], sm[S_CB1 + 4 * tx + 1]);
            ull b23 = pk2(sm[S_CB1 + 4 * tx + 2], sm[S_CB1 + 4 * tx + 3]);
#pragma unroll
            for (int r = 0; r < 4; r++) { acc[r][0] = b01; acc[r][1] = b23; }
            const float* pa = sm + S_M2 + ty * 65;
#pragma unroll 4
            for (int c = 0; c < 64; c++) {
                ulonglong2 w = pc1[c * 16];
                ull A0 = pk2(pa[c], pa[c]);
                ull A1 = pk2(pa[c + 16 * 65], pa[c + 16 * 65]);
                ull A2 = pk2(pa[c + 32 * 65], pa[c + 32 * 65]);
                ull A3 = pk2(pa[c + 48 * 65], pa[c + 48 * 65]);
                fma2(acc[0][0], A0, w.x); fma2(acc[0][1], A0, w.y);
                fma2(acc[1][0], A1, w.x); fma2(acc[1][1], A1, w.y);
                fma2(acc[2][0], A2, w.x); fma2(acc[2][1], A2, w.y);
                fma2(acc[3][0], A3, w.x); fma2(acc[3][1], A3, w.y);
            }
            float cwa = sm[S_CW2 + 4 * tx],     cwb = sm[S_CW2 + 4 * tx + 1];
            float cwc = sm[S_CW2 + 4 * tx + 2], cwd = sm[S_CW2 + 4 * tx + 3];
#pragma unroll
            for (int r = 0; r < 4; r++) {
                float2 v0 = upk2(acc[r][0]), v1 = upk2(acc[r][1]);
                float p = siluf(v0.x) * cwa + siluf(v0.y) * cwb
                        + siluf(v1.x) * cwc + siluf(v1.y) * cwd;
                p += __shfl_xor_sync(0xffffffffu, p, 1);
                p += __shfl_xor_sync(0xffffffffu, p, 2);
                p += __shfl_xor_sync(0xffffffffu, p, 4);
                p += __shfl_xor_sync(0xffffffffu, p, 8);
                if (tx == 0) {
                    int jj = ty + 16 * r;
                    int j = j0 + jj;
                    float em = (j == i) ? 0.f : nmi * sm[S_NM + j];
                    float ph = tanhf(p) * CRANGE * em;
                    cA0 += sm[S_DIFFN + jj * 3 + 0] * ph;
                    cA1 += sm[S_DIFFN + jj * 3 + 1] * ph;
                    cA2 += sm[S_DIFFN + jj * 3 + 2] * ph;
                }
            }
        }
        __syncthreads();
    }

    // ---- epilogue: coord out + fused node update + next-layer H1 ----
    if (tx == 0) {
        sm[S_RED + ty * 3 + 0] = cA0;
        sm[S_RED + ty * 3 + 1] = cA1;
        sm[S_RED + ty * 3 + 2] = cA2;
    }
    if (tid < 64) {
        sm[S_MS + tid] = g_h[bn * 64 + tid];   // h_old
        sm[S_MS + 64 + tid] = aggr;            // agg  (src = [h_old ; agg])
    }
    __syncthreads();
    if (tid < 3) {
        float s = 0.f;
#pragma unroll
        for (int q = 0; q < 16; q++) s += sm[S_RED + q * 3 + tid];
        cOut[bn * 3 + tid] = (sm[S_COORD + i * 3 + tid] + s) * nmi;
    }
    if (l < NL - 1) {
        int k = tid >> 2, q = tid & 3;
        // st = silu(nw1 @ [h;agg] + nb1)
        {
            const float* w1 = nw1 + ((size_t)l * 64 + k) * 128 + q * 32;
            const float* src = sm + S_MS + q * 32;
            float acc = 0.f;
#pragma unroll
            for (int c = 0; c < 32; c++) acc += w1[c] * src[c];
            acc += __shfl_xor_sync(0xffffffffu, acc, 1);
            acc += __shfl_xor_sync(0xffffffffu, acc, 2);
            if (q == 0) sm[S_MS + 128 + k] = siluf(acc + nb1[l * 64 + k]);
        }
        __syncthreads();
        // h_new = (h_old + nw2 @ st + nb2) * nm
        {
            const float* w2 = nw2 + ((size_t)l * 64 + k) * 64 + q * 16;
            const float* stp = sm + S_MS + 128 + q * 16;
            float u = 0.f;
#pragma unroll
            for (int c = 0; c < 16; c++) u += w2[c] * stp[c];
            u += __shfl_xor_sync(0xffffffffu, u, 1);
            u += __shfl_xor_sync(0xffffffffu, u, 2);
            if (q == 0) {
                float hn = (sm[S_MS + k] + u + nb2[l * 64 + k]) * nmi;
                sm[S_MS + 192 + k] = hn;
                g_h[bn * 64 + k] = hn;
            }
        }
        __syncthreads();
        // next-layer H1A/H1B from h_new (H1B into the OTHER buffer: no race)
        {
            const float* w1n = ew1 + ((size_t)(l + 1) * 64 + k) * 130 + q * 16;
            const float* hp = sm + S_MS + 192 + q * 16;
            float a = 0.f, bv = 0.f;
#pragma unroll
            for (int c = 0; c < 16; c++) { a += w1n[c] * hp[c]; bv += w1n[64 + c] * hp[c]; }
            a  += __shfl_xor_sync(0xffffffffu, a, 1);
            a  += __shfl_xor_sync(0xffffffffu, a, 2);
            bv += __shfl_xor_sync(0xffffffffu, bv, 1);
            bv += __shfl_xor_sync(0xffffffffu, bv, 2);
            if (q == 0) {
                g_H1A[bn * 64 + k] = a + eb1[(l + 1) * 64 + k];
                h1bOut[bn * 64 + k] = bv;
            }
        }
    }
}

// ---------------- final: vel + remove mean ----------------
__global__ void k_final(const float* __restrict__ nm, float* __restrict__ out) {
    int b = blockIdx.x;
    int j = threadIdx.x;                     // 256 threads
    __shared__ float rs[256 * 4];
    int bn = b * 256 + j;
    float nmv = nm[bn];
    float v0 = (g_coordA[bn * 3 + 0] - g_x0[bn * 3 + 0]) * nmv;
    float v1 = (g_coordA[bn * 3 + 1] - g_x0[bn * 3 + 1]) * nmv;
    float v2 = (g_coordA[bn * 3 + 2] - g_x0[bn * 3 + 2]) * nmv;
    rs[j] = v0; rs[256 + j] = v1; rs[512 + j] = v2; rs[768 + j] = nmv;
    __syncthreads();
    for (int o = 128; o > 0; o >>= 1) {
        if (j < o) {
            rs[j] += rs[j + o];
            rs[256 + j] += rs[256 + j + o];
            rs[512 + j] += rs[512 + j + o];
            rs[768 + j] += rs[768 + j + o];
        }
        __syncthreads();
    }
    float inv = 1.f / rs[768];
    float m0 = rs[0] * inv, m1 = rs[256] * inv, m2 = rs[512] * inv;
    out[b * 768 + j * 3 + 0] = v0 - m0 * nmv;
    out[b * 768 + j * 3 + 1] = v1 - m1 * nmv;
    out[b * 768 + j * 3 + 2] = v2 - m2 * nmv;
}

// ---------------- launch ----------------
extern "C" void kernel_launch(void* const* d_in, const int* in_sizes, int n_in,
                              void* d_out, int out_size) {
    (void)in_sizes; (void)n_in; (void)out_size;
    const float* t     = (const float*)d_in[0];
    const float* x     = (const float*)d_in[1];
    const float* at    = (const float*)d_in[2];
    const float* aat   = (const float*)d_in[3];
    const float* aap   = (const float*)d_in[4];
    const float* nm    = (const float*)d_in[5];
    const float* emb_w = (const float*)d_in[6];
    const float* emb_b = (const float*)d_in[7];
    const float* ew1   = (const float*)d_in[8];
    const float* eb1   = (const float*)d_in[9];
    const float* ew2   = (const float*)d_in[10];
    const float* eb2   = (const float*)d_in[11];
    const float* nw1   = (const float*)d_in[12];
    const float* nb1   = (const float*)d_in[13];
    const float* nw2   = (const float*)d_in[14];
    const float* nb2   = (const float*)d_in[15];
    const float* cw1   = (const float*)d_in[16];
    const float* cb1   = (const float*)d_in[17];
    const float* aw    = (const float*)d_in[18];
    const float* ab    = (const float*)d_in[19];
    const float* cw2   = (const float*)d_in[20];
    float* out = (float*)d_out;

    cudaFuncSetAttribute(k_edge, cudaFuncAttributeMaxDynamicSharedMemorySize, SMEM_BYTES);

    k_init<<<BN, 256>>>(t, x, at, aat, aap, nm, emb_w, emb_b, ew1, eb1);
    for (int l = 0; l < NL; l++) {
        k_edge<<<BN, 256, SMEM_BYTES>>>(l, ew1, eb1, ew2, eb2,
                                        nw1, nb1, nw2, nb2, cw1, cb1, aw, ab, cw2, nm);
    }
    k_final<<<NB, 256>>>(nm, out);
}

// round 4
// speedup vs baseline: 1.3840x; 1.2807x over previous
#include <cuda_runtime.h>

#define NB 8
#define NN 256
#define BN (NB*NN)          // 2048 nodes
#define HD 64
#define NL 4
#define CRANGE 3.75f        // 15.0 / 4 layers

// ---------------- device scratch ----------------
__device__ float g_h[BN*HD];
__device__ float g_H1A[BN*HD];
__device__ float g_H1B[2][BN*HD];   // double-buffered across layers
__device__ float g_E0[BN*NN];       // edge_attr0, layer-invariant
__device__ float g_coordA[BN*3];
__device__ float g_coordB[BN*3];
__device__ float g_x0[BN*3];

__device__ __forceinline__ float siluf(float x) { return x / (1.f + __expf(-x)); }
__device__ __forceinline__ float sigmf(float x) { return 1.f / (1.f + __expf(-x)); }

typedef unsigned long long ull;
__device__ __forceinline__ ull pk2(float x, float y) {
    ull r; asm("mov.b64 %0, {%1,%2};" : "=l"(r) : "f"(x), "f"(y)); return r;
}
__device__ __forceinline__ void fma2(ull& d, ull a, ull b) {
    asm("fma.rn.f32x2 %0, %1, %2, %0;" : "+l"(d) : "l"(a), "l"(b));
}
__device__ __forceinline__ float2 upk2(ull v) {
    float2 f; asm("mov.b64 {%0,%1}, %2;" : "=f"(f.x), "=f"(f.y) : "l"(v)); return f;
}

// ---------------- init: x0, coord, embedding, layer-0 H1A/H1B, E0 ----------------
__global__ void k_init(const float* __restrict__ t, const float* __restrict__ x,
                       const float* __restrict__ at, const float* __restrict__ aat,
                       const float* __restrict__ aap, const float* __restrict__ nm,
                       const float* __restrict__ emb_w, const float* __restrict__ emb_b,
                       const float* __restrict__ ew1, const float* __restrict__ eb1) {
    int bn = blockIdx.x;
    int b = bn >> 8, i = bn & 255;
    int tid = threadIdx.x;                   // 256 threads
    __shared__ float sh[HD];
    float nmv = nm[bn];
    float xi0 = x[b * 768 + i * 3 + 0] * nmv;
    float xi1 = x[b * 768 + i * 3 + 1] * nmv;
    float xi2 = x[b * 768 + i * 3 + 2] * nmv;
    if (tid < 3) {
        float v = x[b * 768 + i * 3 + tid] * nmv;
        g_x0[bn * 3 + tid] = v;
        g_coordA[bn * 3 + tid] = v;
    }
    // edge_attr0 for all j (layer-invariant)
    {
        float nmj = nm[b * 256 + tid];
        float dx = xi0 - x[b * 768 + tid * 3 + 0] * nmj;
        float dy = xi1 - x[b * 768 + tid * 3 + 1] * nmj;
        float dz = xi2 - x[b * 768 + tid * 3 + 2] * nmj;
        g_E0[bn * 256 + tid] = dx * dx + dy * dy + dz * dz;
    }
    if (tid < 64) {
        float f0 = at[bn] * nmv, f1 = aat[bn] * nmv, f2 = aap[bn] * nmv, f3 = t[b] * nmv;
        float h = emb_b[tid] + emb_w[tid * 4 + 0] * f0 + emb_w[tid * 4 + 1] * f1
                + emb_w[tid * 4 + 2] * f2 + emb_w[tid * 4 + 3] * f3;
        g_h[bn * HD + tid] = h;
        sh[tid] = h;
    }
    __syncthreads();
    int k = tid >> 2, q = tid & 3;
    const float* w1 = ew1 + (size_t)k * 130 + q * 16;     // layer 0
    const float* hp = sh + q * 16;
    float a = 0.f, bv = 0.f;
#pragma unroll
    for (int c = 0; c < 16; c++) { a += w1[c] * hp[c]; bv += w1[64 + c] * hp[c]; }
    a  += __shfl_xor_sync(0xffffffffu, a, 1);
    a  += __shfl_xor_sync(0xffffffffu, a, 2);
    bv += __shfl_xor_sync(0xffffffffu, bv, 1);
    bv += __shfl_xor_sync(0xffffffffu, bv, 2);
    if (q == 0) {
        g_H1A[bn * 64 + k] = a + eb1[k];
        g_H1B[0][bn * 64 + k] = bv;
    }
}

// ---------------- edge kernel smem layout (floats), STRIDE 66 ----------------
#define STR 66
#define S_W2T   0
#define S_C1T   4096
#define S_MS    8192
#define S_M2    12416
#define S_COORD 16640
#define S_NM    17408
#define S_E0A   17664
#define S_H1A   17920
#define S_WR    17984
#define S_WE    18048
#define S_B2    18112
#define S_CB1   18176
#define S_AW    18240
#define S_CW2   18304
#define S_RAD   18368
#define S_ATTS  18432
#define S_AGG   18496
#define S_DIFFN 18560
#define S_RED   18752
#define SMEM_FLOATS 18800
#define SMEM_BYTES  (SMEM_FLOATS * 4)

__global__ void __launch_bounds__(256, 3)
k_edge(int l,
       const float* __restrict__ ew1, const float* __restrict__ eb1,
       const float* __restrict__ ew2, const float* __restrict__ eb2,
       const float* __restrict__ nw1, const float* __restrict__ nb1,
       const float* __restrict__ nw2, const float* __restrict__ nb2,
       const float* __restrict__ cw1, const float* __restrict__ cb1,
       const float* __restrict__ aw,  const float* __restrict__ ab,
       const float* __restrict__ cw2, const float* __restrict__ nm) {
    extern __shared__ float sm[];
    int ping = l & 1;
    const float* cIn = ping ? g_coordB : g_coordA;
    float* cOut = ping ? g_coordA : g_coordB;
    const float* h1bIn = g_H1B[ping];
    float* h1bOut = g_H1B[ping ^ 1];

    int tid = threadIdx.x;
    int tx = tid & 15, ty = tid >> 4;
    int bn = blockIdx.x;
    int b = bn >> 8, i = bn & 255;

    // stage weights row-major (stride 65 temp) into MS/M2
    const float* w2g = ew2 + (size_t)l * 4096;
    const float* c1g = cw1 + (size_t)l * 4096;
    for (int e = tid; e < 4096; e += 256) {
        int kk = e >> 6, c = e & 63;
        sm[S_MS + kk * 65 + c] = w2g[e];
        sm[S_M2 + kk * 65 + c] = c1g[e];
    }
    if (tid < 64) {
        sm[S_WR  + tid] = ew1[((size_t)l * 64 + tid) * 130 + 128];
        sm[S_WE  + tid] = ew1[((size_t)l * 64 + tid) * 130 + 129];
        sm[S_B2  + tid] = eb2[l * 64 + tid];
        sm[S_CB1 + tid] = cb1[l * 64 + tid];
        sm[S_AW  + tid] = aw[l * 64 + tid];
        sm[S_CW2 + tid] = cw2[l * 64 + tid];
        sm[S_H1A + tid] = g_H1A[bn * 64 + tid];
        sm[S_AGG + tid] = 0.f;
    }
    for (int e = tid; e < 768; e += 256) sm[S_COORD + e] = cIn[b * 768 + e];
    sm[S_NM + tid] = nm[b * 256 + tid];
    sm[S_E0A + tid] = g_E0[bn * 256 + tid];
    float attb = ab[l];
    float nmi = nm[bn];
    __syncthreads();
    // transpose weights: W2T[c*64+k] = W2[k][c]
    for (int e = tid; e < 4096; e += 256) {
        int c = e >> 6, kk = e & 63;
        sm[S_W2T + c * 64 + kk] = sm[S_MS + kk * 65 + c];
        sm[S_C1T + c * 64 + kk] = sm[S_M2 + kk * 65 + c];
    }
    __syncthreads();

    float cix = sm[S_COORD + i * 3], ciy = sm[S_COORD + i * 3 + 1], ciz = sm[S_COORD + i * 3 + 2];

    float cA0 = 0.f, cA1 = 0.f, cA2 = 0.f;   // valid for tx==0

    const ulonglong2* pw2 = (const ulonglong2*)(sm + S_W2T) + tx;
    const ulonglong2* pc1 = (const ulonglong2*)(sm + S_C1T) + tx;

    for (int tile = 0; tile < 4; tile++) {
        int j0 = tile * 64;
        // phase A: geometry (tid<64) + previous-tile agg finalize (tid 64..127)
        if (tid < 64) {
            int j = j0 + tid;
            float dx = cix - sm[S_COORD + j * 3];
            float dy = ciy - sm[S_COORD + j * 3 + 1];
            float dz = ciz - sm[S_COORD + j * 3 + 2];
            float rad = dx * dx + dy * dy + dz * dz;
            float inv = 1.f / (sqrtf(rad + 1e-8f) + 1.f);
            sm[S_RAD + tid] = rad;
            sm[S_DIFFN + tid * 3 + 0] = dx * inv;
            sm[S_DIFFN + tid * 3 + 1] = dy * inv;
            sm[S_DIFFN + tid * 3 + 2] = dz * inv;
        } else if (tid < 128 && tile > 0) {
            int c = tid - 64;
            sm[S_AGG + c] += sm[S_MS + c] + sm[S_MS + 64 + c]
                           + sm[S_MS + 128 + c] + sm[S_MS + 192 + c];
        }
        __syncthreads();
        // phase B: Mpre + silu -> MS (float2)
        const float* h1bg = h1bIn + ((size_t)(b * 256 + j0)) * 64;
        for (int p = tid; p < 2048; p += 256) {
            int jj = p >> 5, q = (p & 31) * 2;
            float2 hb = *(const float2*)(h1bg + jj * 64 + q);
            float rad = sm[S_RAD + jj], e0 = sm[S_E0A + j0 + jj];
            float v0 = sm[S_H1A + q]     + hb.x + sm[S_WR + q]     * rad + sm[S_WE + q]     * e0;
            float v1 = sm[S_H1A + q + 1] + hb.y + sm[S_WR + q + 1] * rad + sm[S_WE + q + 1] * e0;
            float2 o; o.x = siluf(v0); o.y = siluf(v1);
            *(float2*)(sm + S_MS + jj * STR + q) = o;
        }
        __syncthreads();
        // phase C: GEMM1: M2 = silu(Ms @ W2^T + b2)
        {
            ull acc[4][2];
            ull b01 = pk2(sm[S_B2 + 4 * tx], sm[S_B2 + 4 * tx + 1]);
            ull b23 = pk2(sm[S_B2 + 4 * tx + 2], sm[S_B2 + 4 * tx + 3]);
#pragma unroll
            for (int r = 0; r < 4; r++) { acc[r][0] = b01; acc[r][1] = b23; }
            const float* pa = sm + S_MS + ty * STR;
#pragma unroll 8
            for (int c2 = 0; c2 < 32; c2++) {
                ulonglong2 w0 = pw2[(2 * c2) * 16];
                ulonglong2 w1 = pw2[(2 * c2 + 1) * 16];
                float2 a0 = *(const float2*)(pa + 2 * c2);
                float2 a1 = *(const float2*)(pa + 2 * c2 + 16 * STR);
                float2 a2 = *(const float2*)(pa + 2 * c2 + 32 * STR);
                float2 a3 = *(const float2*)(pa + 2 * c2 + 48 * STR);
                ull A;
                A = pk2(a0.x, a0.x); fma2(acc[0][0], A, w0.x); fma2(acc[0][1], A, w0.y);
                A = pk2(a0.y, a0.y); fma2(acc[0][0], A, w1.x); fma2(acc[0][1], A, w1.y);
                A = pk2(a1.x, a1.x); fma2(acc[1][0], A, w0.x); fma2(acc[1][1], A, w0.y);
                A = pk2(a1.y, a1.y); fma2(acc[1][0], A, w1.x); fma2(acc[1][1], A, w1.y);
                A = pk2(a2.x, a2.x); fma2(acc[2][0], A, w0.x); fma2(acc[2][1], A, w0.y);
                A = pk2(a2.y, a2.y); fma2(acc[2][0], A, w1.x); fma2(acc[2][1], A, w1.y);
                A = pk2(a3.x, a3.x); fma2(acc[3][0], A, w0.x); fma2(acc[3][1], A, w0.y);
                A = pk2(a3.y, a3.y); fma2(acc[3][0], A, w1.x); fma2(acc[3][1], A, w1.y);
            }
#pragma unroll
            for (int r = 0; r < 4; r++) {
                float2 v0 = upk2(acc[r][0]), v1 = upk2(acc[r][1]);
                float* dst = sm + S_M2 + (ty + 16 * r) * STR + 4 * tx;
                float2 o0; o0.x = siluf(v0.x); o0.y = siluf(v0.y);
                float2 o1; o1.x = siluf(v1.x); o1.y = siluf(v1.y);
                *(float2*)(dst) = o0;
                *(float2*)(dst + 2) = o1;
            }
        }
        __syncthreads();
        // phase D: attention (all 256 threads)
        {
            int row = tid >> 2, q = tid & 3;
            const float* pr = sm + S_M2 + row * STR + q * 16;
            const float* pw = sm + S_AW + q * 16;
            float dot = 0.f;
#pragma unroll
            for (int c = 0; c < 16; c++) dot += pr[c] * pw[c];
            dot += __shfl_xor_sync(0xffffffffu, dot, 1);
            dot += __shfl_xor_sync(0xffffffffu, dot, 2);
            if (q == 0) {
                int j = j0 + row;
                float em = (j == i) ? 0.f : nmi * sm[S_NM + j];
                sm[S_ATTS + row] = sigmf(dot + attb) * em;
            }
        }
        __syncthreads();
        // phase E: GEMM2 (+phi+coord) with atts folded in epilogue; agg partials
        {
            ull acc[4][2];
#pragma unroll
            for (int r = 0; r < 4; r++) { acc[r][0] = 0; acc[r][1] = 0; }
            const float* pa = sm + S_M2 + ty * STR;
#pragma unroll 8
            for (int c2 = 0; c2 < 32; c2++) {
                ulonglong2 w0 = pc1[(2 * c2) * 16];
                ulonglong2 w1 = pc1[(2 * c2 + 1) * 16];
                float2 a0 = *(const float2*)(pa + 2 * c2);
                float2 a1 = *(const float2*)(pa + 2 * c2 + 16 * STR);
                float2 a2 = *(const float2*)(pa + 2 * c2 + 32 * STR);
                float2 a3 = *(const float2*)(pa + 2 * c2 + 48 * STR);
                ull A;
                A = pk2(a0.x, a0.x); fma2(acc[0][0], A, w0.x); fma2(acc[0][1], A, w0.y);
                A = pk2(a0.y, a0.y); fma2(acc[0][0], A, w1.x); fma2(acc[0][1], A, w1.y);
                A = pk2(a1.x, a1.x); fma2(acc[1][0], A, w0.x); fma2(acc[1][1], A, w0.y);
                A = pk2(a1.y, a1.y); fma2(acc[1][0], A, w1.x); fma2(acc[1][1], A, w1.y);
                A = pk2(a2.x, a2.x); fma2(acc[2][0], A, w0.x); fma2(acc[2][1], A, w0.y);
                A = pk2(a2.y, a2.y); fma2(acc[2][0], A, w1.x); fma2(acc[2][1], A, w1.y);
                A = pk2(a3.x, a3.x); fma2(acc[3][0], A, w0.x); fma2(acc[3][1], A, w0.y);
                A = pk2(a3.y, a3.y); fma2(acc[3][0], A, w1.x); fma2(acc[3][1], A, w1.y);
            }
            float cba = sm[S_CB1 + 4 * tx],     cbb = sm[S_CB1 + 4 * tx + 1];
            float cbc = sm[S_CB1 + 4 * tx + 2], cbd = sm[S_CB1 + 4 * tx + 3];
            float cwa = sm[S_CW2 + 4 * tx],     cwb = sm[S_CW2 + 4 * tx + 1];
            float cwc = sm[S_CW2 + 4 * tx + 2], cwd = sm[S_CW2 + 4 * tx + 3];
#pragma unroll
            for (int r = 0; r < 4; r++) {
                int jj = ty + 16 * r;
                float sr = sm[S_ATTS + jj];
                float2 v0 = upk2(acc[r][0]), v1 = upk2(acc[r][1]);
                float va = fmaf(sr, v0.x, cba);
                float vb = fmaf(sr, v0.y, cbb);
                float vc = fmaf(sr, v1.x, cbc);
                float vd = fmaf(sr, v1.y, cbd);
                float p = siluf(va) * cwa + siluf(vb) * cwb
                        + siluf(vc) * cwc + siluf(vd) * cwd;
                p += __shfl_xor_sync(0xffffffffu, p, 1);
                p += __shfl_xor_sync(0xffffffffu, p, 2);
                p += __shfl_xor_sync(0xffffffffu, p, 4);
                p += __shfl_xor_sync(0xffffffffu, p, 8);
                if (tx == 0) {
                    int j = j0 + jj;
                    float em = (j == i) ? 0.f : nmi * sm[S_NM + j];
                    float ph = tanhf(p) * CRANGE * em;
                    cA0 += sm[S_DIFFN + jj * 3 + 0] * ph;
                    cA1 += sm[S_DIFFN + jj * 3 + 1] * ph;
                    cA2 += sm[S_DIFFN + jj * 3 + 2] * ph;
                }
            }
            // agg partials: channel = tid&63, quarter = tid>>6, scaled by atts
            int c = tid & 63, pp = tid >> 6;
            const float* pm = sm + S_M2 + (pp * 16) * STR + c;
            float s = 0.f;
#pragma unroll
            for (int jj = 0; jj < 16; jj++) s += pm[jj * STR] * sm[S_ATTS + pp * 16 + jj];
            sm[S_MS + pp * 64 + c] = s;
        }
        __syncthreads();
    }
    // finalize last tile's agg
    if (tid < 64) {
        sm[S_AGG + tid] += sm[S_MS + tid] + sm[S_MS + 64 + tid]
                         + sm[S_MS + 128 + tid] + sm[S_MS + 192 + tid];
    }
    if (tx == 0) {
        sm[S_RED + ty * 3 + 0] = cA0;
        sm[S_RED + ty * 3 + 1] = cA1;
        sm[S_RED + ty * 3 + 2] = cA2;
    }
    __syncthreads();
    // ---- epilogue: coord out + fused node update + next-layer H1 ----
    if (tid < 64) {
        sm[S_MS + tid] = g_h[bn * 64 + tid];       // h_old
        sm[S_MS + 64 + tid] = sm[S_AGG + tid];     // agg
    }
    __syncthreads();
    if (tid < 3) {
        float s = 0.f;
#pragma unroll
        for (int q = 0; q < 16; q++) s += sm[S_RED + q * 3 + tid];
        cOut[bn * 3 + tid] = (sm[S_COORD + i * 3 + tid] + s) * nmi;
    }
    if (l < NL - 1) {
        int k = tid >> 2, q = tid & 3;
        {
            const float* w1 = nw1 + ((size_t)l * 64 + k) * 128 + q * 32;
            const float* src = sm + S_MS + q * 32;
            float acc = 0.f;
#pragma unroll
            for (int c = 0; c < 32; c++) acc += w1[c] * src[c];
            acc += __shfl_xor_sync(0xffffffffu, acc, 1);
            acc += __shfl_xor_sync(0xffffffffu, acc, 2);
            if (q == 0) sm[S_MS + 128 + k] = siluf(acc + nb1[l * 64 + k]);
        }
        __syncthreads();
        {
            const float* w2 = nw2 + ((size_t)l * 64 + k) * 64 + q * 16;
            const float* stp = sm + S_MS + 128 + q * 16;
            float u = 0.f;
#pragma unroll
            for (int c = 0; c < 16; c++) u += w2[c] * stp[c];
            u += __shfl_xor_sync(0xffffffffu, u, 1);
            u += __shfl_xor_sync(0xffffffffu, u, 2);
            if (q == 0) {
                float hn = (sm[S_MS + k] + u + nb2[l * 64 + k]) * nmi;
                sm[S_MS + 192 + k] = hn;
                g_h[bn * 64 + k] = hn;
            }
        }
        __syncthreads();
        {
            const float* w1n = ew1 + ((size_t)(l + 1) * 64 + k) * 130 + q * 16;
            const float* hp = sm + S_MS + 192 + q * 16;
            float a = 0.f, bv = 0.f;
#pragma unroll
            for (int c = 0; c < 16; c++) { a += w1n[c] * hp[c]; bv += w1n[64 + c] * hp[c]; }
            a  += __shfl_xor_sync(0xffffffffu, a, 1);
            a  += __shfl_xor_sync(0xffffffffu, a, 2);
            bv += __shfl_xor_sync(0xffffffffu, bv, 1);
            bv += __shfl_xor_sync(0xffffffffu, bv, 2);
            if (q == 0) {
                g_H1A[bn * 64 + k] = a + eb1[(l + 1) * 64 + k];
                h1bOut[bn * 64 + k] = bv;
            }
        }
    }
}

// ---------------- final: vel + remove mean ----------------
__global__ void k_final(const float* __restrict__ nm, float* __restrict__ out) {
    int b = blockIdx.x;
    int j = threadIdx.x;                     // 256 threads
    __shared__ float rs[256 * 4];
    int bn = b * 256 + j;
    float nmv = nm[bn];
    float v0 = (g_coordA[bn * 3 + 0] - g_x0[bn * 3 + 0]) * nmv;
    float v1 = (g_coordA[bn * 3 + 1] - g_x0[bn * 3 + 1]) * nmv;
    float v2 = (g_coordA[bn * 3 + 2] - g_x0[bn * 3 + 2]) * nmv;
    rs[j] = v0; rs[256 + j] = v1; rs[512 + j] = v2; rs[768 + j] = nmv;
    __syncthreads();
    for (int o = 128; o > 0; o >>= 1) {
        if (j < o) {
            rs[j] += rs[j + o];
            rs[256 + j] += rs[256 + j + o];
            rs[512 + j] += rs[512 + j + o];
            rs[768 + j] += rs[768 + j + o];
        }
        __syncthreads();
    }
    float inv = 1.f / rs[768];
    float m0 = rs[0] * inv, m1 = rs[256] * inv, m2 = rs[512] * inv;
    out[b * 768 + j * 3 + 0] = v0 - m0 * nmv;
    out[b * 768 + j * 3 + 1] = v1 - m1 * nmv;
    out[b * 768 + j * 3 + 2] = v2 - m2 * nmv;
}

// ---------------- launch ----------------
extern "C" void kernel_launch(void* const* d_in, const int* in_sizes, int n_in,
                              void* d_out, int out_size) {
    (void)in_sizes; (void)n_in; (void)out_size;
    const float* t     = (const float*)d_in[0];
    const float* x     = (const float*)d_in[1];
    const float* at    = (const float*)d_in[2];
    const float* aat   = (const float*)d_in[3];
    const float* aap   = (const float*)d_in[4];
    const float* nm    = (const float*)d_in[5];
    const float* emb_w = (const float*)d_in[6];
    const float* emb_b = (const float*)d_in[7];
    const float* ew1   = (const float*)d_in[8];
    const float* eb1   = (const float*)d_in[9];
    const float* ew2   = (const float*)d_in[10];
    const float* eb2   = (const float*)d_in[11];
    const float* nw1   = (const float*)d_in[12];
    const float* nb1   = (const float*)d_in[13];
    const float* nw2   = (const float*)d_in[14];
    const float* nb2   = (const float*)d_in[15];
    const float* cw1   = (const float*)d_in[16];
    const float* cb1   = (const float*)d_in[17];
    const float* aw    = (const float*)d_in[18];
    const float* ab    = (const float*)d_in[19];
    const float* cw2   = (const float*)d_in[20];
    float* out = (float*)d_out;

    cudaFuncSetAttribute(k_edge, cudaFuncAttributeMaxDynamicSharedMemorySize, SMEM_BYTES);

    k_init<<<BN, 256>>>(t, x, at, aat, aap, nm, emb_w, emb_b, ew1, eb1);
    for (int l = 0; l < NL; l++) {
        k_edge<<<BN, 256, SMEM_BYTES>>>(l, ew1, eb1, ew2, eb2,
                                        nw1, nb1, nw2, nb2, cw1, cb1, aw, ab, cw2, nm);
    }
    k_final<<<NB, 256>>>(nm, out);
}

// round 5
// speedup vs baseline: 1.4396x; 1.0402x over previous
#include <cuda_runtime.h>

#define NB 8
#define NN 256
#define BN (NB*NN)          // 2048 nodes
#define HD 64
#define NL 4
#define CRANGE 3.75f        // 15.0 / 4 layers

// ---------------- device scratch ----------------
__device__ __align__(16) float g_h[BN*HD];
__device__ __align__(16) float g_H1A[BN*HD];
__device__ __align__(16) float g_H1B[2][BN*HD];   // double-buffered across layers
__device__ __align__(16) float g_E0[BN*NN];       // edge_attr0, layer-invariant
__device__ __align__(16) float g_coordA[BN*3];
__device__ __align__(16) float g_coordB[BN*3];
__device__ __align__(16) float g_x0[BN*3];

__device__ __forceinline__ float siluf(float x) { return x / (1.f + __expf(-x)); }
__device__ __forceinline__ float sigmf(float x) { return 1.f / (1.f + __expf(-x)); }

typedef unsigned long long ull;
__device__ __forceinline__ ull pk2(float x, float y) {
    ull r; asm("mov.b64 %0, {%1,%2};" : "=l"(r) : "f"(x), "f"(y)); return r;
}
__device__ __forceinline__ void fma2(ull& d, ull a, ull b) {
    asm("fma.rn.f32x2 %0, %1, %2, %0;" : "+l"(d) : "l"(a), "l"(b));
}
__device__ __forceinline__ float2 upk2(ull v) {
    float2 f; asm("mov.b64 {%0,%1}, %2;" : "=f"(f.x), "=f"(f.y) : "l"(v)); return f;
}

// ---------------- init: x0, coord, embedding, layer-0 H1A/H1B, E0 ----------------
__global__ void k_init(const float* __restrict__ t, const float* __restrict__ x,
                       const float* __restrict__ at, const float* __restrict__ aat,
                       const float* __restrict__ aap, const float* __restrict__ nm,
                       const float* __restrict__ emb_w, const float* __restrict__ emb_b,
                       const float* __restrict__ ew1, const float* __restrict__ eb1) {
    int bn = blockIdx.x;
    int b = bn >> 8, i = bn & 255;
    int tid = threadIdx.x;                   // 256 threads
    __shared__ float sh[HD];
    float nmv = nm[bn];
    float xi0 = x[b * 768 + i * 3 + 0] * nmv;
    float xi1 = x[b * 768 + i * 3 + 1] * nmv;
    float xi2 = x[b * 768 + i * 3 + 2] * nmv;
    if (tid < 3) {
        float v = x[b * 768 + i * 3 + tid] * nmv;
        g_x0[bn * 3 + tid] = v;
        g_coordA[bn * 3 + tid] = v;
    }
    {
        float nmj = nm[b * 256 + tid];
        float dx = xi0 - x[b * 768 + tid * 3 + 0] * nmj;
        float dy = xi1 - x[b * 768 + tid * 3 + 1] * nmj;
        float dz = xi2 - x[b * 768 + tid * 3 + 2] * nmj;
        g_E0[bn * 256 + tid] = dx * dx + dy * dy + dz * dz;
    }
    if (tid < 64) {
        float f0 = at[bn] * nmv, f1 = aat[bn] * nmv, f2 = aap[bn] * nmv, f3 = t[b] * nmv;
        float h = emb_b[tid] + emb_w[tid * 4 + 0] * f0 + emb_w[tid * 4 + 1] * f1
                + emb_w[tid * 4 + 2] * f2 + emb_w[tid * 4 + 3] * f3;
        g_h[bn * HD + tid] = h;
        sh[tid] = h;
    }
    __syncthreads();
    int k = tid >> 2, q = tid & 3;
    const float* w1 = ew1 + (size_t)k * 130 + q * 16;     // layer 0
    const float* hp = sh + q * 16;
    float a = 0.f, bv = 0.f;
#pragma unroll
    for (int c = 0; c < 16; c++) { a += w1[c] * hp[c]; bv += w1[64 + c] * hp[c]; }
    a  += __shfl_xor_sync(0xffffffffu, a, 1);
    a  += __shfl_xor_sync(0xffffffffu, a, 2);
    bv += __shfl_xor_sync(0xffffffffu, bv, 1);
    bv += __shfl_xor_sync(0xffffffffu, bv, 2);
    if (q == 0) {
        g_H1A[bn * 64 + k] = a + eb1[k];
        g_H1B[0][bn * 64 + k] = bv;
    }
}

// ---------------- edge kernel smem layout (floats), STRIDE 68 ----------------
#define STR 68
#define S_W2T   0
#define S_C1T   4096
#define S_MS    8192
#define S_M2    12544
#define S_COORD 16896
#define S_H1A   17664
#define S_WR    17728
#define S_WE    17792
#define S_B2    17856
#define S_CB1   17920
#define S_AW    17984
#define S_CW2   18048
#define S_RAD   18112
#define S_ATTS  18176
#define S_DIFFN 18240
#define S_ATTP  18432
#define SMEM_FLOATS 18944
#define SMEM_BYTES  (SMEM_FLOATS * 4)

__global__ void __launch_bounds__(256, 3)
k_edge(int l,
       const float* __restrict__ ew1, const float* __restrict__ eb1,
       const float* __restrict__ ew2, const float* __restrict__ eb2,
       const float* __restrict__ nw1, const float* __restrict__ nb1,
       const float* __restrict__ nw2, const float* __restrict__ nb2,
       const float* __restrict__ cw1, const float* __restrict__ cb1,
       const float* __restrict__ aw,  const float* __restrict__ ab,
       const float* __restrict__ cw2, const float* __restrict__ nm) {
    extern __shared__ float sm[];
    int ping = l & 1;
    const float* cIn = ping ? g_coordB : g_coordA;
    float* cOut = ping ? g_coordA : g_coordB;
    const float* h1bIn = g_H1B[ping];
    float* h1bOut = g_H1B[ping ^ 1];

    int tid = threadIdx.x;
    int tx = tid & 15, ty = tid >> 4;
    int bn = blockIdx.x;
    int b = bn >> 8, i = bn & 255;

    // stage weights row-major (stride 65 temp) into MS/M2
    const float* w2g = ew2 + (size_t)l * 4096;
    const float* c1g = cw1 + (size_t)l * 4096;
    for (int e = tid; e < 4096; e += 256) {
        int kk = e >> 6, c = e & 63;
        sm[S_MS + kk * 65 + c] = w2g[e];
        sm[S_M2 + kk * 65 + c] = c1g[e];
    }
    if (tid < 64) {
        sm[S_WR  + tid] = ew1[((size_t)l * 64 + tid) * 130 + 128];
        sm[S_WE  + tid] = ew1[((size_t)l * 64 + tid) * 130 + 129];
        sm[S_B2  + tid] = eb2[l * 64 + tid];
        sm[S_CB1 + tid] = cb1[l * 64 + tid];
        sm[S_AW  + tid] = aw[l * 64 + tid];
        sm[S_CW2 + tid] = cw2[l * 64 + tid];
        sm[S_H1A + tid] = g_H1A[bn * 64 + tid];
    }
    for (int e = tid; e < 768; e += 256) sm[S_COORD + e] = cIn[b * 768 + e];
    float attb = ab[l];
    float nmi = nm[bn];
    __syncthreads();
    // transpose weights: W2T[c*64+k] = W2[k][c]
    for (int e = tid; e < 4096; e += 256) {
        int c = e >> 6, kk = e & 63;
        sm[S_W2T + c * 64 + kk] = sm[S_MS + kk * 65 + c];
        sm[S_C1T + c * 64 + kk] = sm[S_M2 + kk * 65 + c];
    }
    __syncthreads();

    float cix = sm[S_COORD + i * 3], ciy = sm[S_COORD + i * 3 + 1], ciz = sm[S_COORD + i * 3 + 2];

    float aggr = 0.f;                        // running agg: threads 64..127, channel tid-64
    float cA0 = 0.f, cA1 = 0.f, cA2 = 0.f;   // valid for tx==0

    const ulonglong2* pw2 = (const ulonglong2*)(sm + S_W2T) + tx;
    const ulonglong2* pc1 = (const ulonglong2*)(sm + S_C1T) + tx;

    for (int tile = 0; tile < 4; tile++) {
        int j0 = tile * 64;
        // phase A: geometry (tid<64) + previous-tile agg accumulate (tid 64..127)
        if (tid < 64) {
            int j = j0 + tid;
            float dx = cix - sm[S_COORD + j * 3];
            float dy = ciy - sm[S_COORD + j * 3 + 1];
            float dz = ciz - sm[S_COORD + j * 3 + 2];
            float rad = dx * dx + dy * dy + dz * dz;
            float inv = 1.f / (sqrtf(rad + 1e-8f) + 1.f);
            sm[S_RAD + tid] = rad;
            sm[S_DIFFN + tid * 3 + 0] = dx * inv;
            sm[S_DIFFN + tid * 3 + 1] = dy * inv;
            sm[S_DIFFN + tid * 3 + 2] = dz * inv;
        } else if (tid < 128 && tile > 0) {
            int c = tid - 64;
            aggr += sm[S_MS + c] + sm[S_MS + 64 + c]
                  + sm[S_MS + 128 + c] + sm[S_MS + 192 + c];
        }
        __syncthreads();
        // phase B: Mpre + silu -> MS (float4)
        const float* h1bg = h1bIn + ((size_t)(b * 256 + j0)) * 64;
        const float* e0g = g_E0 + bn * 256 + j0;
        for (int p = tid; p < 1024; p += 256) {
            int jj = p >> 4, q4 = (p & 15) * 4;
            float4 hb = *(const float4*)(h1bg + jj * 64 + q4);
            float rad = sm[S_RAD + jj];
            float e0 = __ldg(e0g + jj);
            float4 o;
            o.x = siluf(sm[S_H1A + q4]     + hb.x + sm[S_WR + q4]     * rad + sm[S_WE + q4]     * e0);
            o.y = siluf(sm[S_H1A + q4 + 1] + hb.y + sm[S_WR + q4 + 1] * rad + sm[S_WE + q4 + 1] * e0);
            o.z = siluf(sm[S_H1A + q4 + 2] + hb.z + sm[S_WR + q4 + 2] * rad + sm[S_WE + q4 + 2] * e0);
            o.w = siluf(sm[S_H1A + q4 + 3] + hb.w + sm[S_WR + q4 + 3] * rad + sm[S_WE + q4 + 3] * e0);
            *(float4*)(sm + S_MS + jj * STR + q4) = o;
        }
        __syncthreads();
        // phase C: GEMM1 (4-k step, LDS.128 A); epilogue: write M2, att partials
        {
            ull acc[4][2];
            ull b01 = pk2(sm[S_B2 + 4 * tx], sm[S_B2 + 4 * tx + 1]);
            ull b23 = pk2(sm[S_B2 + 4 * tx + 2], sm[S_B2 + 4 * tx + 3]);
#pragma unroll
            for (int r = 0; r < 4; r++) { acc[r][0] = b01; acc[r][1] = b23; }
            const float* pa = sm + S_MS + ty * STR;
#pragma unroll 4
            for (int k4 = 0; k4 < 16; k4++) {
                float4 a0 = *(const float4*)(pa + 4 * k4);
                float4 a1 = *(const float4*)(pa + 4 * k4 + 16 * STR);
                float4 a2 = *(const float4*)(pa + 4 * k4 + 32 * STR);
                float4 a3 = *(const float4*)(pa + 4 * k4 + 48 * STR);
                ulonglong2 w0 = pw2[(4 * k4 + 0) * 16];
                ulonglong2 w1 = pw2[(4 * k4 + 1) * 16];
                ulonglong2 w2 = pw2[(4 * k4 + 2) * 16];
                ulonglong2 w3 = pw2[(4 * k4 + 3) * 16];
                ull A;
                A = pk2(a0.x, a0.x); fma2(acc[0][0], A, w0.x); fma2(acc[0][1], A, w0.y);
                A = pk2(a0.y, a0.y); fma2(acc[0][0], A, w1.x); fma2(acc[0][1], A, w1.y);
                A = pk2(a0.z, a0.z); fma2(acc[0][0], A, w2.x); fma2(acc[0][1], A, w2.y);
                A = pk2(a0.w, a0.w); fma2(acc[0][0], A, w3.x); fma2(acc[0][1], A, w3.y);
                A = pk2(a1.x, a1.x); fma2(acc[1][0], A, w0.x); fma2(acc[1][1], A, w0.y);
                A = pk2(a1.y, a1.y); fma2(acc[1][0], A, w1.x); fma2(acc[1][1], A, w1.y);
                A = pk2(a1.z, a1.z); fma2(acc[1][0], A, w2.x); fma2(acc[1][1], A, w2.y);
                A = pk2(a1.w, a1.w); fma2(acc[1][0], A, w3.x); fma2(acc[1][1], A, w3.y);
                A = pk2(a2.x, a2.x); fma2(acc[2][0], A, w0.x); fma2(acc[2][1], A, w0.y);
                A = pk2(a2.y, a2.y); fma2(acc[2][0], A, w1.x); fma2(acc[2][1], A, w1.y);
                A = pk2(a2.z, a2.z); fma2(acc[2][0], A, w2.x); fma2(acc[2][1], A, w2.y);
                A = pk2(a2.w, a2.w); fma2(acc[2][0], A, w3.x); fma2(acc[2][1], A, w3.y);
                A = pk2(a3.x, a3.x); fma2(acc[3][0], A, w0.x); fma2(acc[3][1], A, w0.y);
                A = pk2(a3.y, a3.y); fma2(acc[3][0], A, w1.x); fma2(acc[3][1], A, w1.y);
                A = pk2(a3.z, a3.z); fma2(acc[3][0], A, w2.x); fma2(acc[3][1], A, w2.y);
                A = pk2(a3.w, a3.w); fma2(acc[3][0], A, w3.x); fma2(acc[3][1], A, w3.y);
            }
            float awa = sm[S_AW + 4 * tx],     awb = sm[S_AW + 4 * tx + 1];
            float awc = sm[S_AW + 4 * tx + 2], awd = sm[S_AW + 4 * tx + 3];
#pragma unroll
            for (int r = 0; r < 4; r++) {
                float2 v0 = upk2(acc[r][0]), v1 = upk2(acc[r][1]);
                float m0 = siluf(v0.x), m1 = siluf(v0.y), m2 = siluf(v1.x), m3 = siluf(v1.y);
                float4 o; o.x = m0; o.y = m1; o.z = m2; o.w = m3;
                *(float4*)(sm + S_M2 + (ty + 16 * r) * STR + 4 * tx) = o;
                float ap = m0 * awa + m1 * awb + m2 * awc + m3 * awd;
                ap += __shfl_xor_sync(0xffffffffu, ap, 8);
                if (tx < 8) sm[S_ATTP + (ty + 16 * r) * 8 + tx] = ap;
            }
        }
        __syncthreads();
        // phase D': attention finalize from 8-wide partials
        {
            int row = tid >> 2, q = tid & 3;
            float2 apv = *(const float2*)(sm + S_ATTP + row * 8 + 2 * q);
            float dot = apv.x + apv.y;
            dot += __shfl_xor_sync(0xffffffffu, dot, 1);
            dot += __shfl_xor_sync(0xffffffffu, dot, 2);
            if (q == 0) {
                int j = j0 + row;
                float em = (j == i) ? 0.f : nmi * __ldg(nm + b * 256 + j);
                sm[S_ATTS + row] = sigmf(dot + attb) * em;
            }
        }
        __syncthreads();
        // phase E: GEMM2 (+phi+coord, atts folded) + agg partials
        {
            ull acc[4][2];
#pragma unroll
            for (int r = 0; r < 4; r++) { acc[r][0] = 0; acc[r][1] = 0; }
            const float* pa = sm + S_M2 + ty * STR;
#pragma unroll 4
            for (int k4 = 0; k4 < 16; k4++) {
                float4 a0 = *(const float4*)(pa + 4 * k4);
                float4 a1 = *(const float4*)(pa + 4 * k4 + 16 * STR);
                float4 a2 = *(const float4*)(pa + 4 * k4 + 32 * STR);
                float4 a3 = *(const float4*)(pa + 4 * k4 + 48 * STR);
                ulonglong2 w0 = pc1[(4 * k4 + 0) * 16];
                ulonglong2 w1 = pc1[(4 * k4 + 1) * 16];
                ulonglong2 w2 = pc1[(4 * k4 + 2) * 16];
                ulonglong2 w3 = pc1[(4 * k4 + 3) * 16];
                ull A;
                A = pk2(a0.x, a0.x); fma2(acc[0][0], A, w0.x); fma2(acc[0][1], A, w0.y);
                A = pk2(a0.y, a0.y); fma2(acc[0][0], A, w1.x); fma2(acc[0][1], A, w1.y);
                A = pk2(a0.z, a0.z); fma2(acc[0][0], A, w2.x); fma2(acc[0][1], A, w2.y);
                A = pk2(a0.w, a0.w); fma2(acc[0][0], A, w3.x); fma2(acc[0][1], A, w3.y);
                A = pk2(a1.x, a1.x); fma2(acc[1][0], A, w0.x); fma2(acc[1][1], A, w0.y);
                A = pk2(a1.y, a1.y); fma2(acc[1][0], A, w1.x); fma2(acc[1][1], A, w1.y);
                A = pk2(a1.z, a1.z); fma2(acc[1][0], A, w2.x); fma2(acc[1][1], A, w2.y);
                A = pk2(a1.w, a1.w); fma2(acc[1][0], A, w3.x); fma2(acc[1][1], A, w3.y);
                A = pk2(a2.x, a2.x); fma2(acc[2][0], A, w0.x); fma2(acc[2][1], A, w0.y);
                A = pk2(a2.y, a2.y); fma2(acc[2][0], A, w1.x); fma2(acc[2][1], A, w1.y);
                A = pk2(a2.z, a2.z); fma2(acc[2][0], A, w2.x); fma2(acc[2][1], A, w2.y);
                A = pk2(a2.w, a2.w); fma2(acc[2][0], A, w3.x); fma2(acc[2][1], A, w3.y);
                A = pk2(a3.x, a3.x); fma2(acc[3][0], A, w0.x); fma2(acc[3][1], A, w0.y);
                A = pk2(a3.y, a3.y); fma2(acc[3][0], A, w1.x); fma2(acc[3][1], A, w1.y);
                A = pk2(a3.z, a3.z); fma2(acc[3][0], A, w2.x); fma2(acc[3][1], A, w2.y);
                A = pk2(a3.w, a3.w); fma2(acc[3][0], A, w3.x); fma2(acc[3][1], A, w3.y);
            }
            float cba = sm[S_CB1 + 4 * tx],     cbb = sm[S_CB1 + 4 * tx + 1];
            float cbc = sm[S_CB1 + 4 * tx + 2], cbd = sm[S_CB1 + 4 * tx + 3];
            float cwa = sm[S_CW2 + 4 * tx],     cwb = sm[S_CW2 + 4 * tx + 1];
            float cwc = sm[S_CW2 + 4 * tx + 2], cwd = sm[S_CW2 + 4 * tx + 3];
#pragma unroll
            for (int r = 0; r < 4; r++) {
                int jj = ty + 16 * r;
                float sr = sm[S_ATTS + jj];
                float2 v0 = upk2(acc[r][0]), v1 = upk2(acc[r][1]);
                float va = fmaf(sr, v0.x, cba);
                float vb = fmaf(sr, v0.y, cbb);
                float vc = fmaf(sr, v1.x, cbc);
                float vd = fmaf(sr, v1.y, cbd);
                float p = siluf(va) * cwa + siluf(vb) * cwb
                        + siluf(vc) * cwc + siluf(vd) * cwd;
                p += __shfl_xor_sync(0xffffffffu, p, 1);
                p += __shfl_xor_sync(0xffffffffu, p, 2);
                p += __shfl_xor_sync(0xffffffffu, p, 4);
                p += __shfl_xor_sync(0xffffffffu, p, 8);
                if (tx == 0) {
                    int j = j0 + jj;
                    float em = (j == i) ? 0.f : nmi * __ldg(nm + b * 256 + j);
                    float ph = tanhf(p) * CRANGE * em;
                    cA0 += sm[S_DIFFN + jj * 3 + 0] * ph;
                    cA1 += sm[S_DIFFN + jj * 3 + 1] * ph;
                    cA2 += sm[S_DIFFN + jj * 3 + 2] * ph;
                }
            }
            // agg partials: channel = tid&63, quarter = tid>>6, scaled by atts
            int c = tid & 63, pp = tid >> 6;
            const float* pm = sm + S_M2 + (pp * 16) * STR + c;
            float s = 0.f;
#pragma unroll
            for (int jj = 0; jj < 16; jj++) s += pm[jj * STR] * sm[S_ATTS + pp * 16 + jj];
            sm[S_MS + pp * 64 + c] = s;
        }
        __syncthreads();
    }
    // finalize last tile's agg + stage for node update
    if (tid >= 64 && tid < 128) {
        int c = tid - 64;
        aggr += sm[S_MS + c] + sm[S_MS + 64 + c]
              + sm[S_MS + 128 + c] + sm[S_MS + 192 + c];
        sm[S_M2 + tid] = aggr;                  // [64..127] = agg
    }
    if (tid < 64) sm[S_M2 + tid] = g_h[bn * 64 + tid];   // [0..63] = h_old
    if (tx == 0) {
        sm[S_ATTP + ty * 3 + 0] = cA0;
        sm[S_ATTP + ty * 3 + 1] = cA1;
        sm[S_ATTP + ty * 3 + 2] = cA2;
    }
    __syncthreads();
    if (tid < 3) {
        float s = 0.f;
#pragma unroll
        for (int q = 0; q < 16; q++) s += sm[S_ATTP + q * 3 + tid];
        cOut[bn * 3 + tid] = (sm[S_COORD + i * 3 + tid] + s) * nmi;
    }
    if (l < NL - 1) {
        int k = tid >> 2, q = tid & 3;
        {
            const float* w1 = nw1 + ((size_t)l * 64 + k) * 128 + q * 32;
            const float* src = sm + S_M2 + q * 32;
            float acc = 0.f;
#pragma unroll
            for (int c = 0; c < 32; c++) acc += w1[c] * src[c];
            acc += __shfl_xor_sync(0xffffffffu, acc, 1);
            acc += __shfl_xor_sync(0xffffffffu, acc, 2);
            if (q == 0) sm[S_M2 + 128 + k] = siluf(acc + nb1[l * 64 + k]);
        }
        __syncthreads();
        {
            const float* w2 = nw2 + ((size_t)l * 64 + k) * 64 + q * 16;
            const float* stp = sm + S_M2 + 128 + q * 16;
            float u = 0.f;
#pragma unroll
            for (int c = 0; c < 16; c++) u += w2[c] * stp[c];
            u += __shfl_xor_sync(0xffffffffu, u, 1);
            u += __shfl_xor_sync(0xffffffffu, u, 2);
            if (q == 0) {
                float hn = (sm[S_M2 + k] + u + nb2[l * 64 + k]) * nmi;
                sm[S_M2 + 192 + k] = hn;
                g_h[bn * 64 + k] = hn;
            }
        }
        __syncthreads();
        {
            const float* w1n = ew1 + ((size_t)(l + 1) * 64 + k) * 130 + q * 16;
            const float* hp = sm + S_M2 + 192 + q * 16;
            float a = 0.f, bv = 0.f;
#pragma unroll
            for (int c = 0; c < 16; c++) { a += w1n[c] * hp[c]; bv += w1n[64 + c] * hp[c]; }
            a  += __shfl_xor_sync(0xffffffffu, a, 1);
            a  += __shfl_xor_sync(0xffffffffu, a, 2);
            bv += __shfl_xor_sync(0xffffffffu, bv, 1);
            bv += __shfl_xor_sync(0xffffffffu, bv, 2);
            if (q == 0) {
                g_H1A[bn * 64 + k] = a + eb1[(l + 1) * 64 + k];
                h1bOut[bn * 64 + k] = bv;
            }
        }
    }
}

// ---------------- final: vel + remove mean ----------------
__global__ void k_final(const float* __restrict__ nm, float* __restrict__ out) {
    int b = blockIdx.x;
    int j = threadIdx.x;                     // 256 threads
    __shared__ float rs[256 * 4];
    int bn = b * 256 + j;
    float nmv = nm[bn];
    float v0 = (g_coordA[bn * 3 + 0] - g_x0[bn * 3 + 0]) * nmv;
    float v1 = (g_coordA[bn * 3 + 1] - g_x0[bn * 3 + 1]) * nmv;
    float v2 = (g_coordA[bn * 3 + 2] - g_x0[bn * 3 + 2]) * nmv;
    rs[j] = v0; rs[256 + j] = v1; rs[512 + j] = v2; rs[768 + j] = nmv;
    __syncthreads();
    for (int o = 128; o > 0; o >>= 1) {
        if (j < o) {
            rs[j] += rs[j + o];
            rs[256 + j] += rs[256 + j + o];
            rs[512 + j] += rs[512 + j + o];
            rs[768 + j] += rs[768 + j + o];
        }
        __syncthreads();
    }
    float inv = 1.f / rs[768];
    float m0 = rs[0] * inv, m1 = rs[256] * inv, m2 = rs[512] * inv;
    out[b * 768 + j * 3 + 0] = v0 - m0 * nmv;
    out[b * 768 + j * 3 + 1] = v1 - m1 * nmv;
    out[b * 768 + j * 3 + 2] = v2 - m2 * nmv;
}

// ---------------- launch ----------------
extern "C" void kernel_launch(void* const* d_in, const int* in_sizes, int n_in,
                              void* d_out, int out_size) {
    (void)in_sizes; (void)n_in; (void)out_size;
    const float* t     = (const float*)d_in[0];
    const float* x     = (const float*)d_in[1];
    const float* at    = (const float*)d_in[2];
    const float* aat   = (const float*)d_in[3];
    const float* aap   = (const float*)d_in[4];
    const float* nm    = (const float*)d_in[5];
    const float* emb_w = (const float*)d_in[6];
    const float* emb_b = (const float*)d_in[7];
    const float* ew1   = (const float*)d_in[8];
    const float* eb1   = (const float*)d_in[9];
    const float* ew2   = (const float*)d_in[10];
    const float* eb2   = (const float*)d_in[11];
    const float* nw1   = (const float*)d_in[12];
    const float* nb1   = (const float*)d_in[13];
    const float* nw2   = (const float*)d_in[14];
    const float* nb2   = (const float*)d_in[15];
    const float* cw1   = (const float*)d_in[16];
    const float* cb1   = (const float*)d_in[17];
    const float* aw    = (const float*)d_in[18];
    const float* ab    = (const float*)d_in[19];
    const float* cw2   = (const float*)d_in[20];
    float* out = (float*)d_out;

    cudaFuncSetAttribute(k_edge, cudaFuncAttributeMaxDynamicSharedMemorySize, SMEM_BYTES);

    k_init<<<BN, 256>>>(t, x, at, aat, aap, nm, emb_w, emb_b, ew1, eb1);
    for (int l = 0; l < NL; l++) {
        k_edge<<<BN, 256, SMEM_BYTES>>>(l, ew1, eb1, ew2, eb2,
                                        nw1, nb1, nw2, nb2, cw1, cb1, aw, ab, cw2, nm);
    }
    k_final<<<NB, 256>>>(nm, out);
}

// round 6
// speedup vs baseline: 2.5158x; 1.7475x over previous
#include <cuda_runtime.h>
#include <cuda_fp16.h>
#include <cstdint>

#define NB 8
#define NN 256
#define BN (NB*NN)          // 2048 nodes
#define HD 64
#define NL 4
#define CRANGE 3.75f        // 15.0 / 4 layers

// ---------------- device scratch ----------------
__device__ __align__(16) float g_h[BN*HD];
__device__ __align__(16) float g_H1A[BN*HD];
__device__ __align__(16) float g_H1B[2][BN*HD];
__device__ __align__(16) float g_E0[BN*NN];
__device__ __align__(16) float g_coordA[BN*3];
__device__ __align__(16) float g_coordB[BN*3];
__device__ __align__(16) float g_x0[BN*3];

__device__ __forceinline__ float siluf(float x) { return x / (1.f + __expf(-x)); }
__device__ __forceinline__ float sigmf(float x) { return 1.f / (1.f + __expf(-x)); }

// ---------------- HMMA helpers ----------------
#define LDSM4(r0,r1,r2,r3, addr) \
    asm volatile("ldmatrix.sync.aligned.m8n8.x4.shared.b16 {%0,%1,%2,%3}, [%4];" \
        : "=r"(r0), "=r"(r1), "=r"(r2), "=r"(r3) : "r"(addr))

#define MMA16816(d, a0,a1,a2,a3, b0,b1) \
    asm volatile("mma.sync.aligned.m16n8k16.row.col.f32.f16.f16.f32 " \
        "{%0,%1,%2,%3}, {%4,%5,%6,%7}, {%8,%9}, {%0,%1,%2,%3};" \
        : "+f"(d[0]), "+f"(d[1]), "+f"(d[2]), "+f"(d[3]) \
        : "r"(a0), "r"(a1), "r"(a2), "r"(a3), "r"(b0), "r"(b1))

// ---------------- init: x0, coord, embedding, layer-0 H1A/H1B, E0 ----------------
__global__ void k_init(const float* __restrict__ t, const float* __restrict__ x,
                       const float* __restrict__ at, const float* __restrict__ aat,
                       const float* __restrict__ aap, const float* __restrict__ nm,
                       const float* __restrict__ emb_w, const float* __restrict__ emb_b,
                       const float* __restrict__ ew1, const float* __restrict__ eb1) {
    int bn = blockIdx.x;
    int b = bn >> 8, i = bn & 255;
    int tid = threadIdx.x;                   // 256 threads
    __shared__ float sh[HD];
    float nmv = nm[bn];
    float xi0 = x[b * 768 + i * 3 + 0] * nmv;
    float xi1 = x[b * 768 + i * 3 + 1] * nmv;
    float xi2 = x[b * 768 + i * 3 + 2] * nmv;
    if (tid < 3) {
        float v = x[b * 768 + i * 3 + tid] * nmv;
        g_x0[bn * 3 + tid] = v;
        g_coordA[bn * 3 + tid] = v;
    }
    {
        float nmj = nm[b * 256 + tid];
        float dx = xi0 - x[b * 768 + tid * 3 + 0] * nmj;
        float dy = xi1 - x[b * 768 + tid * 3 + 1] * nmj;
        float dz = xi2 - x[b * 768 + tid * 3 + 2] * nmj;
        g_E0[bn * 256 + tid] = dx * dx + dy * dy + dz * dz;
    }
    if (tid < 64) {
        float f0 = at[bn] * nmv, f1 = aat[bn] * nmv, f2 = aap[bn] * nmv, f3 = t[b] * nmv;
        float h = emb_b[tid] + emb_w[tid * 4 + 0] * f0 + emb_w[tid * 4 + 1] * f1
                + emb_w[tid * 4 + 2] * f2 + emb_w[tid * 4 + 3] * f3;
        g_h[bn * HD + tid] = h;
        sh[tid] = h;
    }
    __syncthreads();
    int k = tid >> 2, q = tid & 3;
    const float* w1 = ew1 + (size_t)k * 130 + q * 16;     // layer 0
    const float* hp = sh + q * 16;
    float a = 0.f, bv = 0.f;
#pragma unroll
    for (int c = 0; c < 16; c++) { a += w1[c] * hp[c]; bv += w1[64 + c] * hp[c]; }
    a  += __shfl_xor_sync(0xffffffffu, a, 1);
    a  += __shfl_xor_sync(0xffffffffu, a, 2);
    bv += __shfl_xor_sync(0xffffffffu, bv, 1);
    bv += __shfl_xor_sync(0xffffffffu, bv, 2);
    if (q == 0) {
        g_H1A[bn * 64 + k] = a + eb1[k];
        g_H1B[0][bn * 64 + k] = bv;
    }
}

// ---------------- edge kernel smem layout ----------------
// fp16 tiles (half indices), stride 72 halfs (144B rows -> ldmatrix conflict-free)
#define H_W2   0
#define H_C1   4608
#define H_MS   9216
#define H_M2   13824
// fp32 region (float indices); halves occupy floats [0, 9216)
#define S_COORD 9216
#define S_RAD   9984
#define S_DIFFN 10240
#define S_H1A   11008
#define S_WR    11072
#define S_WE    11136
#define S_B2    11200
#define S_CB1   11264
#define S_AW    11328
#define S_CW2   11392
#define S_ATTS  11456
#define S_ATTP  11520
#define S_PHIP  11648
#define S_CA0   11776
#define S_CA1   11840
#define S_CA2   11904
#define S_AGGP  11968
#define S_UPD   12224
#define SMEM_FLOATS 12480
#define SMEM_BYTES  (SMEM_FLOATS * 4)

__global__ void __launch_bounds__(256, 3)
k_edge(int l,
       const float* __restrict__ ew1, const float* __restrict__ eb1,
       const float* __restrict__ ew2, const float* __restrict__ eb2,
       const float* __restrict__ nw1, const float* __restrict__ nb1,
       const float* __restrict__ nw2, const float* __restrict__ nb2,
       const float* __restrict__ cw1, const float* __restrict__ cb1,
       const float* __restrict__ aw,  const float* __restrict__ ab,
       const float* __restrict__ cw2, const float* __restrict__ nm) {
    extern __shared__ float sm[];
    __half* smh = (__half*)sm;
    int ping = l & 1;
    const float* cIn = ping ? g_coordB : g_coordA;
    float* cOut = ping ? g_coordA : g_coordB;
    const float* h1bIn = g_H1B[ping];
    float* h1bOut = g_H1B[ping ^ 1];

    int tid = threadIdx.x;
    int wid = tid >> 5, lane = tid & 31;
    int t4 = lane >> 2, tq = lane & 3;
    int mrow = (wid & 3) << 4;            // GEMM row-tile base (j)
    int nhalf = (wid >> 2) << 5;          // GEMM col-half base (out channel)
    int whalf = wid >> 2;
    int bn = blockIdx.x;
    int b = bn >> 8, i = bn & 255;

    // ---- stage weights (fp16) + vectors + coords ----
    const float* w2g = ew2 + (size_t)l * 4096;
    const float* c1g = cw1 + (size_t)l * 4096;
    for (int e = tid; e < 4096; e += 256) {
        int r = e >> 6, c = e & 63;
        smh[H_W2 + r * 72 + c] = __float2half_rn(w2g[e]);
        smh[H_C1 + r * 72 + c] = __float2half_rn(c1g[e]);
    }
    if (tid < 64) {
        sm[S_WR  + tid] = ew1[((size_t)l * 64 + tid) * 130 + 128];
        sm[S_WE  + tid] = ew1[((size_t)l * 64 + tid) * 130 + 129];
        sm[S_B2  + tid] = eb2[l * 64 + tid];
        sm[S_CB1 + tid] = cb1[l * 64 + tid];
        sm[S_AW  + tid] = aw[l * 64 + tid];
        sm[S_CW2 + tid] = cw2[l * 64 + tid];
        sm[S_H1A + tid] = g_H1A[bn * 64 + tid];
        sm[S_CA0 + tid] = 0.f;
        sm[S_CA1 + tid] = 0.f;
        sm[S_CA2 + tid] = 0.f;
    }
    for (int e = tid; e < 768; e += 256) sm[S_COORD + e] = cIn[b * 768 + e];
    float attb = ab[l];
    float nmi = nm[bn];
    __syncthreads();

    // ---- geometry for ALL 256 j (once) ----
    {
        float cix = sm[S_COORD + i * 3], ciy = sm[S_COORD + i * 3 + 1], ciz = sm[S_COORD + i * 3 + 2];
        int j = tid;
        float dx = cix - sm[S_COORD + j * 3];
        float dy = ciy - sm[S_COORD + j * 3 + 1];
        float dz = ciz - sm[S_COORD + j * 3 + 2];
        float rad = dx * dx + dy * dy + dz * dz;
        float inv = 1.f / (sqrtf(rad + 1e-8f) + 1.f);
        sm[S_RAD + j] = rad;
        sm[S_DIFFN + j * 3 + 0] = dx * inv;
        sm[S_DIFFN + j * 3 + 1] = dy * inv;
        sm[S_DIFFN + j * 3 + 2] = dz * inv;
    }
    __syncthreads();

    // ---- ldmatrix lane addressing ----
    uint32_t sbase = (uint32_t)__cvta_generic_to_shared((void*)sm);
    int ar = (lane & 7) + ((lane >> 3) & 1) * 8;       // A: mats 0/2 rows 0-7, 1/3 rows 8-15
    int ac = (lane >> 4) * 8;                          //    mats 2,3 cols +8
    uint32_t aoff = (uint32_t)(((mrow + ar) * 72 + ac) * 2);
    int br = (lane & 7) + ((lane >> 4) ? 8 : 0);       // B: mats 0,1 n 0-7; mats 2,3 n 8-15
    int bc = ((lane >> 3) & 1) * 8;                    //    mats 1,3 k +8
    uint32_t boff = (uint32_t)(((nhalf + br) * 72 + bc) * 2);
    uint32_t aMS = sbase + H_MS * 2 + aoff;
    uint32_t aM2 = sbase + H_M2 * 2 + aoff;
    uint32_t bW2 = sbase + H_W2 * 2 + boff;
    uint32_t bC1 = sbase + H_C1 * 2 + boff;

    float aggr = 0.f;                      // per-thread agg partial (c = tid&63, quarter = tid>>6)
    const float* nmb = nm + b * 256;
    int r0 = mrow + t4, r1 = r0 + 8;       // tile-local rows owned in HMMA epilogues

    for (int tile = 0; tile < 4; tile++) {
        int j0 = tile << 6;
        // ---- phase F (finalize previous tile's phi/coord) + phase B (Mpre+silu -> MSh) ----
        if (tile > 0 && tid < 64) {
            int j = j0 - 64 + tid;
            float p = sm[S_PHIP + tid * 2] + sm[S_PHIP + tid * 2 + 1];
            float em = (j == i) ? 0.f : nmi * __ldg(nmb + j);
            float ph = tanhf(p) * CRANGE * em;
            sm[S_CA0 + tid] += sm[S_DIFFN + j * 3 + 0] * ph;
            sm[S_CA1 + tid] += sm[S_DIFFN + j * 3 + 1] * ph;
            sm[S_CA2 + tid] += sm[S_DIFFN + j * 3 + 2] * ph;
        }
        const float* h1bg = h1bIn + ((size_t)(b * 256 + j0)) * 64;
        const float* e0g = g_E0 + (size_t)bn * 256 + j0;
#pragma unroll
        for (int it = 0; it < 4; it++) {
            int p = tid + it * 256;
            int jj = p >> 4, q4 = (p & 15) * 4;
            float4 hb = *(const float4*)(h1bg + jj * 64 + q4);
            float rad = sm[S_RAD + j0 + jj];
            float e0 = __ldg(e0g + jj);
            float v0 = siluf(sm[S_H1A + q4]     + hb.x + sm[S_WR + q4]     * rad + sm[S_WE + q4]     * e0);
            float v1 = siluf(sm[S_H1A + q4 + 1] + hb.y + sm[S_WR + q4 + 1] * rad + sm[S_WE + q4 + 1] * e0);
            float v2 = siluf(sm[S_H1A + q4 + 2] + hb.z + sm[S_WR + q4 + 2] * rad + sm[S_WE + q4 + 2] * e0);
            float v3 = siluf(sm[S_H1A + q4 + 3] + hb.w + sm[S_WR + q4 + 3] * rad + sm[S_WE + q4 + 3] * e0);
            *(__half2*)(smh + H_MS + jj * 72 + q4)     = __floats2half2_rn(v0, v1);
            *(__half2*)(smh + H_MS + jj * 72 + q4 + 2) = __floats2half2_rn(v2, v3);
        }
        __syncthreads();
        // ---- phase C: GEMM1 (HMMA) + epilogue: M2h fp16 + attention partials ----
        {
            float acc[4][4];
#pragma unroll
            for (int nt = 0; nt < 4; nt++)
#pragma unroll
                for (int r = 0; r < 4; r++) acc[nt][r] = 0.f;
#pragma unroll
            for (int kk = 0; kk < 4; kk++) {
                uint32_t a0, a1, a2, a3;
                LDSM4(a0, a1, a2, a3, aMS + kk * 32);
#pragma unroll
                for (int ntp = 0; ntp < 2; ntp++) {
                    uint32_t b0, b1, b2r, b3r;
                    LDSM4(b0, b1, b2r, b3r, bW2 + ntp * 2304 + kk * 32);
                    MMA16816(acc[2 * ntp],     a0, a1, a2, a3, b0, b1);
                    MMA16816(acc[2 * ntp + 1], a0, a1, a2, a3, b2r, b3r);
                }
            }
            float ap0 = 0.f, ap1 = 0.f;
#pragma unroll
            for (int nt = 0; nt < 4; nt++) {
                int c0 = nhalf + nt * 8 + 2 * tq;
                float b2a = sm[S_B2 + c0], b2b = sm[S_B2 + c0 + 1];
                float m00 = siluf(acc[nt][0] + b2a);
                float m01 = siluf(acc[nt][1] + b2b);
                float m10 = siluf(acc[nt][2] + b2a);
                float m11 = siluf(acc[nt][3] + b2b);
                *(__half2*)(smh + H_M2 + r0 * 72 + c0) = __floats2half2_rn(m00, m01);
                *(__half2*)(smh + H_M2 + r1 * 72 + c0) = __floats2half2_rn(m10, m11);
                float awa = sm[S_AW + c0], awb = sm[S_AW + c0 + 1];
                ap0 += m00 * awa + m01 * awb;
                ap1 += m10 * awa + m11 * awb;
            }
            ap0 += __shfl_xor_sync(0xffffffffu, ap0, 1);
            ap0 += __shfl_xor_sync(0xffffffffu, ap0, 2);
            ap1 += __shfl_xor_sync(0xffffffffu, ap1, 1);
            ap1 += __shfl_xor_sync(0xffffffffu, ap1, 2);
            if (tq == 0) {
                sm[S_ATTP + r0 * 2 + whalf] = ap0;
                sm[S_ATTP + r1 * 2 + whalf] = ap1;
            }
        }
        __syncthreads();
        // ---- phase D: attention finalize ----
        if (tid < 64) {
            int j = j0 + tid;
            float dot = sm[S_ATTP + tid * 2] + sm[S_ATTP + tid * 2 + 1] + attb;
            float em = (j == i) ? 0.f : nmi * __ldg(nmb + j);
            sm[S_ATTS + tid] = sigmf(dot) * em;
        }
        __syncthreads();
        // ---- phase E: GEMM2 (HMMA, atts folded in epilogue) + phi partials + agg ----
        {
            float acc[4][4];
#pragma unroll
            for (int nt = 0; nt < 4; nt++)
#pragma unroll
                for (int r = 0; r < 4; r++) acc[nt][r] = 0.f;
#pragma unroll
            for (int kk = 0; kk < 4; kk++) {
                uint32_t a0, a1, a2, a3;
                LDSM4(a0, a1, a2, a3, aM2 + kk * 32);
#pragma unroll
                for (int ntp = 0; ntp < 2; ntp++) {
                    uint32_t b0, b1, b2r, b3r;
                    LDSM4(b0, b1, b2r, b3r, bC1 + ntp * 2304 + kk * 32);
                    MMA16816(acc[2 * ntp],     a0, a1, a2, a3, b0, b1);
                    MMA16816(acc[2 * ntp + 1], a0, a1, a2, a3, b2r, b3r);
                }
            }
            float sr0 = sm[S_ATTS + r0], sr1 = sm[S_ATTS + r1];
            float pp0 = 0.f, pp1 = 0.f;
#pragma unroll
            for (int nt = 0; nt < 4; nt++) {
                int c0 = nhalf + nt * 8 + 2 * tq;
                float cba = sm[S_CB1 + c0], cbb = sm[S_CB1 + c0 + 1];
                float cwa = sm[S_CW2 + c0], cwb = sm[S_CW2 + c0 + 1];
                pp0 += siluf(fmaf(sr0, acc[nt][0], cba)) * cwa
                     + siluf(fmaf(sr0, acc[nt][1], cbb)) * cwb;
                pp1 += siluf(fmaf(sr1, acc[nt][2], cba)) * cwa
                     + siluf(fmaf(sr1, acc[nt][3], cbb)) * cwb;
            }
            pp0 += __shfl_xor_sync(0xffffffffu, pp0, 1);
            pp0 += __shfl_xor_sync(0xffffffffu, pp0, 2);
            pp1 += __shfl_xor_sync(0xffffffffu, pp1, 1);
            pp1 += __shfl_xor_sync(0xffffffffu, pp1, 2);
            if (tq == 0) {
                sm[S_PHIP + r0 * 2 + whalf] = pp0;
                sm[S_PHIP + r1 * 2 + whalf] = pp1;
            }
            // agg partial: channel c = tid&63, quarter = tid>>6 (16 rows each)
            int c = tid & 63, pq = tid >> 6;
            const __half* pm = smh + H_M2 + (pq * 16) * 72 + c;
#pragma unroll
            for (int jj = 0; jj < 16; jj++)
                aggr += __half2float(pm[jj * 72]) * sm[S_ATTS + pq * 16 + jj];
        }
        __syncthreads();
    }
    // ---- tail: finalize tile-3 phi/coord, agg reduce, coord out, node update ----
    if (tid < 64) {
        int j = 192 + tid;
        float p = sm[S_PHIP + tid * 2] + sm[S_PHIP + tid * 2 + 1];
        float em = (j == i) ? 0.f : nmi * __ldg(nmb + j);
        float ph = tanhf(p) * CRANGE * em;
        sm[S_CA0 + tid] += sm[S_DIFFN + j * 3 + 0] * ph;
        sm[S_CA1 + tid] += sm[S_DIFFN + j * 3 + 1] * ph;
        sm[S_CA2 + tid] += sm[S_DIFFN + j * 3 + 2] * ph;
    }
    sm[S_AGGP + (tid >> 6) * 64 + (tid & 63)] = aggr;
    __syncthreads();
    if (tid < 64) {
        sm[S_UPD + tid] = g_h[bn * 64 + tid];                        // h_old
        sm[S_UPD + 64 + tid] = sm[S_AGGP + tid] + sm[S_AGGP + 64 + tid]
                             + sm[S_AGGP + 128 + tid] + sm[S_AGGP + 192 + tid];  // agg
    }
    __syncthreads();
    if (tid < 3) {
        float s = 0.f;
#pragma unroll
        for (int q = 0; q < 64; q++) s += sm[S_CA0 + tid * 64 + q];
        cOut[bn * 3 + tid] = (sm[S_COORD + i * 3 + tid] + s) * nmi;
    }
    if (l < NL - 1) {
        int k = tid >> 2, q = tid & 3;
        {
            const float* w1 = nw1 + ((size_t)l * 64 + k) * 128 + q * 32;
            const float* src = sm + S_UPD + q * 32;
            float acc = 0.f;
#pragma unroll
            for (int c = 0; c < 32; c++) acc += w1[c] * src[c];
            acc += __shfl_xor_sync(0xffffffffu, acc, 1);
            acc += __shfl_xor_sync(0xffffffffu, acc, 2);
            if (q == 0) sm[S_UPD + 128 + k] = siluf(acc + nb1[l * 64 + k]);
        }
        __syncthreads();
        {
            const float* w2 = nw2 + ((size_t)l * 64 + k) * 64 + q * 16;
            const float* stp = sm + S_UPD + 128 + q * 16;
            float u = 0.f;
#pragma unroll
            for (int c = 0; c < 16; c++) u += w2[c] * stp[c];
            u += __shfl_xor_sync(0xffffffffu, u, 1);
            u += __shfl_xor_sync(0xffffffffu, u, 2);
            if (q == 0) {
                float hn = (sm[S_UPD + k] + u + nb2[l * 64 + k]) * nmi;
                sm[S_UPD + 192 + k] = hn;
                g_h[bn * 64 + k] = hn;
            }
        }
        __syncthreads();
        {
            const float* w1n = ew1 + ((size_t)(l + 1) * 64 + k) * 130 + q * 16;
            const float* hp = sm + S_UPD + 192 + q * 16;
            float a = 0.f, bv = 0.f;
#pragma unroll
            for (int c = 0; c < 16; c++) { a += w1n[c] * hp[c]; bv += w1n[64 + c] * hp[c]; }
            a  += __shfl_xor_sync(0xffffffffu, a, 1);
            a  += __shfl_xor_sync(0xffffffffu, a, 2);
            bv += __shfl_xor_sync(0xffffffffu, bv, 1);
            bv += __shfl_xor_sync(0xffffffffu, bv, 2);
            if (q == 0) {
                g_H1A[bn * 64 + k] = a + eb1[(l + 1) * 64 + k];
                h1bOut[bn * 64 + k] = bv;
            }
        }
    }
}

// ---------------- final: vel + remove mean ----------------
__global__ void k_final(const float* __restrict__ nm, float* __restrict__ out) {
    int b = blockIdx.x;
    int j = threadIdx.x;                     // 256 threads
    __shared__ float rs[256 * 4];
    int bn = b * 256 + j;
    float nmv = nm[bn];
    float v0 = (g_coordA[bn * 3 + 0] - g_x0[bn * 3 + 0]) * nmv;
    float v1 = (g_coordA[bn * 3 + 1] - g_x0[bn * 3 + 1]) * nmv;
    float v2 = (g_coordA[bn * 3 + 2] - g_x0[bn * 3 + 2]) * nmv;
    rs[j] = v0; rs[256 + j] = v1; rs[512 + j] = v2; rs[768 + j] = nmv;
    __syncthreads();
    for (int o = 128; o > 0; o >>= 1) {
        if (j < o) {
            rs[j] += rs[j + o];
            rs[256 + j] += rs[256 + j + o];
            rs[512 + j] += rs[512 + j + o];
            rs[768 + j] += rs[768 + j + o];
        }
        __syncthreads();
    }
    float inv = 1.f / rs[768];
    float m0 = rs[0] * inv, m1 = rs[256] * inv, m2 = rs[512] * inv;
    out[b * 768 + j * 3 + 0] = v0 - m0 * nmv;
    out[b * 768 + j * 3 + 1] = v1 - m1 * nmv;
    out[b * 768 + j * 3 + 2] = v2 - m2 * nmv;
}

// ---------------- launch ----------------
extern "C" void kernel_launch(void* const* d_in, const int* in_sizes, int n_in,
                              void* d_out, int out_size) {
    (void)in_sizes; (void)n_in; (void)out_size;
    const float* t     = (const float*)d_in[0];
    const float* x     = (const float*)d_in[1];
    const float* at    = (const float*)d_in[2];
    const float* aat   = (const float*)d_in[3];
    const float* aap   = (const float*)d_in[4];
    const float* nm    = (const float*)d_in[5];
    const float* emb_w = (const float*)d_in[6];
    const float* emb_b = (const float*)d_in[7];
    const float* ew1   = (const float*)d_in[8];
    const float* eb1   = (const float*)d_in[9];
    const float* ew2   = (const float*)d_in[10];
    const float* eb2   = (const float*)d_in[11];
    const float* nw1   = (const float*)d_in[12];
    const float* nb1   = (const float*)d_in[13];
    const float* nw2   = (const float*)d_in[14];
    const float* nb2   = (const float*)d_in[15];
    const float* cw1   = (const float*)d_in[16];
    const float* cb1   = (const float*)d_in[17];
    const float* aw    = (const float*)d_in[18];
    const float* ab    = (const float*)d_in[19];
    const float* cw2   = (const float*)d_in[20];
    float* out = (float*)d_out;

    cudaFuncSetAttribute(k_edge, cudaFuncAttributeMaxDynamicSharedMemorySize, SMEM_BYTES);

    k_init<<<BN, 256>>>(t, x, at, aat, aap, nm, emb_w, emb_b, ew1, eb1);
    for (int l = 0; l < NL; l++) {
        k_edge<<<BN, 256, SMEM_BYTES>>>(l, ew1, eb1, ew2, eb2,
                                        nw1, nb1, nw2, nb2, cw1, cb1, aw, ab, cw2, nm);
    }
    k_final<<<NB, 256>>>(nm, out);
}

// round 7
// speedup vs baseline: 2.5512x; 1.0140x over previous
#include <cuda_runtime.h>
#include <cuda_fp16.h>
#include <cstdint>

#define NB 8
#define NN 256
#define BN (NB*NN)          // 2048 nodes
#define HD 64
#define NL 4
#define CRANGE 3.75f        // 15.0 / 4 layers

// ---------------- device scratch ----------------
__device__ __align__(16) float g_h[BN*HD];
__device__ __align__(16) float g_H1A[BN*HD];
__device__ __align__(16) float g_H1B[2][BN*HD];
__device__ __align__(16) float g_E0[BN*NN];
__device__ __align__(16) float g_coordA[BN*3];
__device__ __align__(16) float g_coordB[BN*3];
__device__ __align__(16) float g_x0[BN*3];
__device__ __align__(16) __half g_W2h[NL][64*72];   // padded fp16 weights, ready to copy
__device__ __align__(16) __half g_C1h[NL][64*72];

__device__ __forceinline__ float siluf(float x) { return x / (1.f + __expf(-x)); }
__device__ __forceinline__ float sigmf(float x) { return 1.f / (1.f + __expf(-x)); }

// ---------------- HMMA helpers ----------------
#define LDSM4(r0,r1,r2,r3, addr) \
    asm volatile("ldmatrix.sync.aligned.m8n8.x4.shared.b16 {%0,%1,%2,%3}, [%4];" \
        : "=r"(r0), "=r"(r1), "=r"(r2), "=r"(r3) : "r"(addr))

#define MMA16816(d, a0,a1,a2,a3, b0,b1) \
    asm volatile("mma.sync.aligned.m16n8k16.row.col.f32.f16.f16.f32 " \
        "{%0,%1,%2,%3}, {%4,%5,%6,%7}, {%8,%9}, {%0,%1,%2,%3};" \
        : "+f"(d[0]), "+f"(d[1]), "+f"(d[2]), "+f"(d[3]) \
        : "r"(a0), "r"(a1), "r"(a2), "r"(a3), "r"(b0), "r"(b1))

// ---------------- weight pre-conversion (once per layer) ----------------
__global__ void k_wconv(const float* __restrict__ ew2, const float* __restrict__ cw1) {
    int l = blockIdx.x;
    int tid = threadIdx.x;
    const float* w2g = ew2 + (size_t)l * 4096;
    const float* c1g = cw1 + (size_t)l * 4096;
    for (int e = tid; e < 4096; e += 256) {
        int r = e >> 6, c = e & 63;
        g_W2h[l][r * 72 + c] = __float2half_rn(w2g[e]);
        g_C1h[l][r * 72 + c] = __float2half_rn(c1g[e]);
    }
}

// ---------------- init: x0, coord, embedding, layer-0 H1A/H1B, E0 ----------------
__global__ void k_init(const float* __restrict__ t, const float* __restrict__ x,
                       const float* __restrict__ at, const float* __restrict__ aat,
                       const float* __restrict__ aap, const float* __restrict__ nm,
                       const float* __restrict__ emb_w, const float* __restrict__ emb_b,
                       const float* __restrict__ ew1, const float* __restrict__ eb1) {
    int bn = blockIdx.x;
    int b = bn >> 8, i = bn & 255;
    int tid = threadIdx.x;                   // 256 threads
    __shared__ float sh[HD];
    float nmv = nm[bn];
    float xi0 = x[b * 768 + i * 3 + 0] * nmv;
    float xi1 = x[b * 768 + i * 3 + 1] * nmv;
    float xi2 = x[b * 768 + i * 3 + 2] * nmv;
    if (tid < 3) {
        float v = x[b * 768 + i * 3 + tid] * nmv;
        g_x0[bn * 3 + tid] = v;
        g_coordA[bn * 3 + tid] = v;
    }
    {
        float nmj = nm[b * 256 + tid];
        float dx = xi0 - x[b * 768 + tid * 3 + 0] * nmj;
        float dy = xi1 - x[b * 768 + tid * 3 + 1] * nmj;
        float dz = xi2 - x[b * 768 + tid * 3 + 2] * nmj;
        g_E0[bn * 256 + tid] = dx * dx + dy * dy + dz * dz;
    }
    if (tid < 64) {
        float f0 = at[bn] * nmv, f1 = aat[bn] * nmv, f2 = aap[bn] * nmv, f3 = t[b] * nmv;
        float h = emb_b[tid] + emb_w[tid * 4 + 0] * f0 + emb_w[tid * 4 + 1] * f1
                + emb_w[tid * 4 + 2] * f2 + emb_w[tid * 4 + 3] * f3;
        g_h[bn * HD + tid] = h;
        sh[tid] = h;
    }
    __syncthreads();
    int k = tid >> 2, q = tid & 3;
    const float* w1 = ew1 + (size_t)k * 130 + q * 16;     // layer 0
    const float* hp = sh + q * 16;
    float a = 0.f, bv = 0.f;
#pragma unroll
    for (int c = 0; c < 16; c++) { a += w1[c] * hp[c]; bv += w1[64 + c] * hp[c]; }
    a  += __shfl_xor_sync(0xffffffffu, a, 1);
    a  += __shfl_xor_sync(0xffffffffu, a, 2);
    bv += __shfl_xor_sync(0xffffffffu, bv, 1);
    bv += __shfl_xor_sync(0xffffffffu, bv, 2);
    if (q == 0) {
        g_H1A[bn * 64 + k] = a + eb1[k];
        g_H1B[0][bn * 64 + k] = bv;
    }
}

// ---------------- edge kernel smem layout ----------------
// fp16 tiles (half indices), stride 72 halfs
#define H_W2   0
#define H_C1   4608
#define H_MS   9216
#define H_M2   13824
// fp32 region (float indices); halves occupy floats [0, 9216)
#define S_COORD 9216
#define S_RAD   9984
#define S_DIFFN 10240
#define S_H1A   11008
#define S_WR    11072
#define S_WE    11136
#define S_B2    11200
#define S_CB1   11264
#define S_AW    11328
#define S_CW2   11392
#define S_ATTP  11456
#define S_PHIP  11584
#define S_CA0   11712
#define S_CA1   11776
#define S_CA2   11840
#define S_AGGP  11904
#define S_UPD   12160
#define SMEM_FLOATS 12416
#define SMEM_BYTES  (SMEM_FLOATS * 4)

__global__ void __launch_bounds__(256, 4)
k_edge(int l,
       const float* __restrict__ ew1, const float* __restrict__ eb1,
       const float* __restrict__ ew2, const float* __restrict__ eb2,
       const float* __restrict__ nw1, const float* __restrict__ nb1,
       const float* __restrict__ nw2, const float* __restrict__ nb2,
       const float* __restrict__ cw1, const float* __restrict__ cb1,
       const float* __restrict__ aw,  const float* __restrict__ ab,
       const float* __restrict__ cw2, const float* __restrict__ nm) {
    extern __shared__ float sm[];
    __half* smh = (__half*)sm;
    int ping = l & 1;
    const float* cIn = ping ? g_coordB : g_coordA;
    float* cOut = ping ? g_coordA : g_coordB;
    const float* h1bIn = g_H1B[ping];
    float* h1bOut = g_H1B[ping ^ 1];

    int tid = threadIdx.x;
    int wid = tid >> 5, lane = tid & 31;
    int t4 = lane >> 2, tq = lane & 3;
    int mrow = (wid & 3) << 4;            // GEMM row-tile base (j)
    int nhalf = (wid >> 2) << 5;          // GEMM col-half base (out channel)
    int whalf = wid >> 2;
    int bn = blockIdx.x;
    int b = bn >> 8, i = bn & 255;

    // ---- stage weights (pre-converted fp16, uint4 copy) + vectors + coords ----
    {
        const uint4* sw2 = (const uint4*)(g_W2h[l]);
        const uint4* sc1 = (const uint4*)(g_C1h[l]);
        uint4* dw2 = (uint4*)(smh + H_W2);
        uint4* dc1 = (uint4*)(smh + H_C1);
        for (int e = tid; e < 576; e += 256) { dw2[e] = sw2[e]; dc1[e] = sc1[e]; }
    }
    if (tid < 64) {
        sm[S_WR  + tid] = ew1[((size_t)l * 64 + tid) * 130 + 128];
        sm[S_WE  + tid] = ew1[((size_t)l * 64 + tid) * 130 + 129];
        sm[S_B2  + tid] = eb2[l * 64 + tid];
        sm[S_CB1 + tid] = cb1[l * 64 + tid];
        sm[S_AW  + tid] = aw[l * 64 + tid];
        sm[S_CW2 + tid] = cw2[l * 64 + tid];
        sm[S_H1A + tid] = g_H1A[bn * 64 + tid];
        sm[S_CA0 + tid] = 0.f;
        sm[S_CA1 + tid] = 0.f;
        sm[S_CA2 + tid] = 0.f;
    }
    for (int e = tid; e < 768; e += 256) sm[S_COORD + e] = cIn[b * 768 + e];
    float attb = ab[l];
    float nmi = nm[bn];
    __syncthreads();

    // ---- geometry for ALL 256 j (once) ----
    {
        float cix = sm[S_COORD + i * 3], ciy = sm[S_COORD + i * 3 + 1], ciz = sm[S_COORD + i * 3 + 2];
        int j = tid;
        float dx = cix - sm[S_COORD + j * 3];
        float dy = ciy - sm[S_COORD + j * 3 + 1];
        float dz = ciz - sm[S_COORD + j * 3 + 2];
        float rad = dx * dx + dy * dy + dz * dz;
        float inv = 1.f / (sqrtf(rad + 1e-8f) + 1.f);
        sm[S_RAD + j] = rad;
        sm[S_DIFFN + j * 3 + 0] = dx * inv;
        sm[S_DIFFN + j * 3 + 1] = dy * inv;
        sm[S_DIFFN + j * 3 + 2] = dz * inv;
    }
    __syncthreads();

    // ---- ldmatrix lane addressing ----
    uint32_t sbase = (uint32_t)__cvta_generic_to_shared((void*)sm);
    int ar = (lane & 7) + ((lane >> 3) & 1) * 8;
    int ac = (lane >> 4) * 8;
    uint32_t aoff = (uint32_t)(((mrow + ar) * 72 + ac) * 2);
    int br = (lane & 7) + ((lane >> 4) ? 8 : 0);
    int bc = ((lane >> 3) & 1) * 8;
    uint32_t boff = (uint32_t)(((nhalf + br) * 72 + bc) * 2);
    uint32_t aMS = sbase + H_MS * 2 + aoff;
    uint32_t aM2 = sbase + H_M2 * 2 + aoff;
    uint32_t bW2 = sbase + H_W2 * 2 + boff;
    uint32_t bC1 = sbase + H_C1 * 2 + boff;

    float aggr = 0.f;                      // per-warp agg partial: col = nhalf+lane, rowtile = wid&3
    const float* nmb = nm + b * 256;
    int r0 = mrow + t4, r1 = r0 + 8;

    for (int tile = 0; tile < 4; tile++) {
        int j0 = tile << 6;
        // ---- phase F (finalize previous tile's phi/coord) + phase B (Mpre+silu -> MSh) ----
        if (tile > 0 && tid < 64) {
            int j = j0 - 64 + tid;
            float p = sm[S_PHIP + tid * 2] + sm[S_PHIP + tid * 2 + 1];
            float em = (j == i) ? 0.f : nmi * __ldg(nmb + j);
            float ph = tanhf(p) * CRANGE * em;
            sm[S_CA0 + tid] += sm[S_DIFFN + j * 3 + 0] * ph;
            sm[S_CA1 + tid] += sm[S_DIFFN + j * 3 + 1] * ph;
            sm[S_CA2 + tid] += sm[S_DIFFN + j * 3 + 2] * ph;
        }
        const float* h1bg = h1bIn + ((size_t)(b * 256 + j0)) * 64;
        const float* e0g = g_E0 + (size_t)bn * 256 + j0;
#pragma unroll
        for (int it = 0; it < 4; it++) {
            int p = tid + it * 256;
            int jj = p >> 4, q4 = (p & 15) * 4;
            float4 hb = *(const float4*)(h1bg + jj * 64 + q4);
            float rad = sm[S_RAD + j0 + jj];
            float e0 = __ldg(e0g + jj);
            float v0 = siluf(sm[S_H1A + q4]     + hb.x + sm[S_WR + q4]     * rad + sm[S_WE + q4]     * e0);
            float v1 = siluf(sm[S_H1A + q4 + 1] + hb.y + sm[S_WR + q4 + 1] * rad + sm[S_WE + q4 + 1] * e0);
            float v2 = siluf(sm[S_H1A + q4 + 2] + hb.z + sm[S_WR + q4 + 2] * rad + sm[S_WE + q4 + 2] * e0);
            float v3 = siluf(sm[S_H1A + q4 + 3] + hb.w + sm[S_WR + q4 + 3] * rad + sm[S_WE + q4 + 3] * e0);
            *(__half2*)(smh + H_MS + jj * 72 + q4)     = __floats2half2_rn(v0, v1);
            *(__half2*)(smh + H_MS + jj * 72 + q4 + 2) = __floats2half2_rn(v2, v3);
        }
        __syncthreads();
        // ---- phase C: GEMM1 (HMMA) + epilogue: M2h fp16 + attention partials ----
        {
            float acc[4][4];
#pragma unroll
            for (int nt = 0; nt < 4; nt++)
#pragma unroll
                for (int r = 0; r < 4; r++) acc[nt][r] = 0.f;
#pragma unroll
            for (int kk = 0; kk < 4; kk++) {
                uint32_t a0, a1, a2, a3;
                LDSM4(a0, a1, a2, a3, aMS + kk * 32);
#pragma unroll
                for (int ntp = 0; ntp < 2; ntp++) {
                    uint32_t b0, b1, b2r, b3r;
                    LDSM4(b0, b1, b2r, b3r, bW2 + ntp * 2304 + kk * 32);
                    MMA16816(acc[2 * ntp],     a0, a1, a2, a3, b0, b1);
                    MMA16816(acc[2 * ntp + 1], a0, a1, a2, a3, b2r, b3r);
                }
            }
            float ap0 = 0.f, ap1 = 0.f;
#pragma unroll
            for (int nt = 0; nt < 4; nt++) {
                int c0 = nhalf + nt * 8 + 2 * tq;
                float b2a = sm[S_B2 + c0], b2b = sm[S_B2 + c0 + 1];
                float m00 = siluf(acc[nt][0] + b2a);
                float m01 = siluf(acc[nt][1] + b2b);
                float m10 = siluf(acc[nt][2] + b2a);
                float m11 = siluf(acc[nt][3] + b2b);
                *(__half2*)(smh + H_M2 + r0 * 72 + c0) = __floats2half2_rn(m00, m01);
                *(__half2*)(smh + H_M2 + r1 * 72 + c0) = __floats2half2_rn(m10, m11);
                float awa = sm[S_AW + c0], awb = sm[S_AW + c0 + 1];
                ap0 += m00 * awa + m01 * awb;
                ap1 += m10 * awa + m11 * awb;
            }
            ap0 += __shfl_xor_sync(0xffffffffu, ap0, 1);
            ap0 += __shfl_xor_sync(0xffffffffu, ap0, 2);
            ap1 += __shfl_xor_sync(0xffffffffu, ap1, 1);
            ap1 += __shfl_xor_sync(0xffffffffu, ap1, 2);
            if (tq == 0) {
                sm[S_ATTP + r0 * 2 + whalf] = ap0;
                sm[S_ATTP + r1 * 2 + whalf] = ap1;
            }
        }
        __syncthreads();
        // ---- phase E: atts in-warp, GEMM2 (HMMA), phi partials, agg (shfl) ----
        {
            // lanes 0..15 compute atts for the warp's 16 rows
            float attsOwn = 0.f;
            if (lane < 16) {
                int r = mrow + lane;
                int j = j0 + r;
                float dot = sm[S_ATTP + r * 2] + sm[S_ATTP + r * 2 + 1] + attb;
                float em = (j == i) ? 0.f : nmi * __ldg(nmb + j);
                attsOwn = sigmf(dot) * em;
            }
            float sr0 = __shfl_sync(0xffffffffu, attsOwn, t4);
            float sr1 = __shfl_sync(0xffffffffu, attsOwn, t4 + 8);

            float acc[4][4];
#pragma unroll
            for (int nt = 0; nt < 4; nt++)
#pragma unroll
                for (int r = 0; r < 4; r++) acc[nt][r] = 0.f;
#pragma unroll
            for (int kk = 0; kk < 4; kk++) {
                uint32_t a0, a1, a2, a3;
                LDSM4(a0, a1, a2, a3, aM2 + kk * 32);
#pragma unroll
                for (int ntp = 0; ntp < 2; ntp++) {
                    uint32_t b0, b1, b2r, b3r;
                    LDSM4(b0, b1, b2r, b3r, bC1 + ntp * 2304 + kk * 32);
                    MMA16816(acc[2 * ntp],     a0, a1, a2, a3, b0, b1);
                    MMA16816(acc[2 * ntp + 1], a0, a1, a2, a3, b2r, b3r);
                }
            }
            float pp0 = 0.f, pp1 = 0.f;
#pragma unroll
            for (int nt = 0; nt < 4; nt++) {
                int c0 = nhalf + nt * 8 + 2 * tq;
                float cba = sm[S_CB1 + c0], cbb = sm[S_CB1 + c0 + 1];
                float cwa = sm[S_CW2 + c0], cwb = sm[S_CW2 + c0 + 1];
                pp0 += siluf(fmaf(sr0, acc[nt][0], cba)) * cwa
                     + siluf(fmaf(sr0, acc[nt][1], cbb)) * cwb;
                pp1 += siluf(fmaf(sr1, acc[nt][2], cba)) * cwa
                     + siluf(fmaf(sr1, acc[nt][3], cbb)) * cwb;
            }
            pp0 += __shfl_xor_sync(0xffffffffu, pp0, 1);
            pp0 += __shfl_xor_sync(0xffffffffu, pp0, 2);
            pp1 += __shfl_xor_sync(0xffffffffu, pp1, 1);
            pp1 += __shfl_xor_sync(0xffffffffu, pp1, 2);
            if (tq == 0) {
                sm[S_PHIP + r0 * 2 + whalf] = pp0;
                sm[S_PHIP + r1 * 2 + whalf] = pp1;
            }
            // agg: col = nhalf+lane, warp's own 16 rows, atts via shfl broadcast
            const __half* pm = smh + H_M2 + mrow * 72 + nhalf + lane;
#pragma unroll
            for (int jj = 0; jj < 16; jj++) {
                float aj = __shfl_sync(0xffffffffu, attsOwn, jj);
                aggr += __half2float(pm[jj * 72]) * aj;
            }
        }
        __syncthreads();
    }
    // ---- tail: finalize tile-3 phi/coord, agg partial store, coord out, node update ----
    if (tid < 64) {
        int j = 192 + tid;
        float p = sm[S_PHIP + tid * 2] + sm[S_PHIP + tid * 2 + 1];
        float em = (j == i) ? 0.f : nmi * __ldg(nmb + j);
        float ph = tanhf(p) * CRANGE * em;
        sm[S_CA0 + tid] += sm[S_DIFFN + j * 3 + 0] * ph;
        sm[S_CA1 + tid] += sm[S_DIFFN + j * 3 + 1] * ph;
        sm[S_CA2 + tid] += sm[S_DIFFN + j * 3 + 2] * ph;
    }
    sm[S_AGGP + (wid & 3) * 64 + nhalf + lane] = aggr;
    __syncthreads();
    if (tid < 64) {
        sm[S_UPD + tid] = g_h[bn * 64 + tid];                        // h_old
        sm[S_UPD + 64 + tid] = sm[S_AGGP + tid] + sm[S_AGGP + 64 + tid]
                             + sm[S_AGGP + 128 + tid] + sm[S_AGGP + 192 + tid];  // agg
    }
    __syncthreads();
    if (tid < 3) {
        float s = 0.f;
#pragma unroll
        for (int q = 0; q < 64; q++) s += sm[S_CA0 + tid * 64 + q];
        cOut[bn * 3 + tid] = (sm[S_COORD + i * 3 + tid] + s) * nmi;
    }
    if (l < NL - 1) {
        int k = tid >> 2, q = tid & 3;
        {
            const float* w1 = nw1 + ((size_t)l * 64 + k) * 128 + q * 32;
            const float* src = sm + S_UPD + q * 32;
            float acc = 0.f;
#pragma unroll
            for (int c = 0; c < 32; c++) acc += w1[c] * src[c];
            acc += __shfl_xor_sync(0xffffffffu, acc, 1);
            acc += __shfl_xor_sync(0xffffffffu, acc, 2);
            if (q == 0) sm[S_UPD + 128 + k] = siluf(acc + nb1[l * 64 + k]);
        }
        __syncthreads();
        {
            const float* w2 = nw2 + ((size_t)l * 64 + k) * 64 + q * 16;
            const float* stp = sm + S_UPD + 128 + q * 16;
            float u = 0.f;
#pragma unroll
            for (int c = 0; c < 16; c++) u += w2[c] * stp[c];
            u += __shfl_xor_sync(0xffffffffu, u, 1);
            u += __shfl_xor_sync(0xffffffffu, u, 2);
            if (q == 0) {
                float hn = (sm[S_UPD + k] + u + nb2[l * 64 + k]) * nmi;
                sm[S_UPD + 192 + k] = hn;
                g_h[bn * 64 + k] = hn;
            }
        }
        __syncthreads();
        {
            const float* w1n = ew1 + ((size_t)(l + 1) * 64 + k) * 130 + q * 16;
            const float* hp = sm + S_UPD + 192 + q * 16;
            float a = 0.f, bv = 0.f;
#pragma unroll
            for (int c = 0; c < 16; c++) { a += w1n[c] * hp[c]; bv += w1n[64 + c] * hp[c]; }
            a  += __shfl_xor_sync(0xffffffffu, a, 1);
            a  += __shfl_xor_sync(0xffffffffu, a, 2);
            bv += __shfl_xor_sync(0xffffffffu, bv, 1);
            bv += __shfl_xor_sync(0xffffffffu, bv, 2);
            if (q == 0) {
                g_H1A[bn * 64 + k] = a + eb1[(l + 1) * 64 + k];
                h1bOut[bn * 64 + k] = bv;
            }
        }
    }
}

// ---------------- final: vel + remove mean ----------------
__global__ void k_final(const float* __restrict__ nm, float* __restrict__ out) {
    int b = blockIdx.x;
    int j = threadIdx.x;                     // 256 threads
    __shared__ float rs[256 * 4];
    int bn = b * 256 + j;
    float nmv = nm[bn];
    float v0 = (g_coordA[bn * 3 + 0] - g_x0[bn * 3 + 0]) * nmv;
    float v1 = (g_coordA[bn * 3 + 1] - g_x0[bn * 3 + 1]) * nmv;
    float v2 = (g_coordA[bn * 3 + 2] - g_x0[bn * 3 + 2]) * nmv;
    rs[j] = v0; rs[256 + j] = v1; rs[512 + j] = v2; rs[768 + j] = nmv;
    __syncthreads();
    for (int o = 128; o > 0; o >>= 1) {
        if (j < o) {
            rs[j] += rs[j + o];
            rs[256 + j] += rs[256 + j + o];
            rs[512 + j] += rs[512 + j + o];
            rs[768 + j] += rs[768 + j + o];
        }
        __syncthreads();
    }
    float inv = 1.f / rs[768];
    float m0 = rs[0] * inv, m1 = rs[256] * inv, m2 = rs[512] * inv;
    out[b * 768 + j * 3 + 0] = v0 - m0 * nmv;
    out[b * 768 + j * 3 + 1] = v1 - m1 * nmv;
    out[b * 768 + j * 3 + 2] = v2 - m2 * nmv;
}

// ---------------- launch ----------------
extern "C" void kernel_launch(void* const* d_in, const int* in_sizes, int n_in,
                              void* d_out, int out_size) {
    (void)in_sizes; (void)n_in; (void)out_size;
    const float* t     = (const float*)d_in[0];
    const float* x     = (const float*)d_in[1];
    const float* at    = (const float*)d_in[2];
    const float* aat   = (const float*)d_in[3];
    const float* aap   = (const float*)d_in[4];
    const float* nm    = (const float*)d_in[5];
    const float* emb_w = (const float*)d_in[6];
    const float* emb_b = (const float*)d_in[7];
    const float* ew1   = (const float*)d_in[8];
    const float* eb1   = (const float*)d_in[9];
    const float* ew2   = (const float*)d_in[10];
    const float* eb2   = (const float*)d_in[11];
    const float* nw1   = (const float*)d_in[12];
    const float* nb1   = (const float*)d_in[13];
    const float* nw2   = (const float*)d_in[14];
    const float* nb2   = (const float*)d_in[15];
    const float* cw1   = (const float*)d_in[16];
    const float* cb1   = (const float*)d_in[17];
    const float* aw    = (const float*)d_in[18];
    const float* ab    = (const float*)d_in[19];
    const float* cw2   = (const float*)d_in[20];
    float* out = (float*)d_out;

    cudaFuncSetAttribute(k_edge, cudaFuncAttributeMaxDynamicSharedMemorySize, SMEM_BYTES);

    k_wconv<<<NL, 256>>>(ew2, cw1);
    k_init<<<BN, 256>>>(t, x, at, aat, aap, nm, emb_w, emb_b, ew1, eb1);
    for (int l = 0; l < NL; l++) {
        k_edge<<<BN, 256, SMEM_BYTES>>>(l, ew1, eb1, ew2, eb2,
                                        nw1, nb1, nw2, nb2, cw1, cb1, aw, ab, cw2, nm);
    }
    k_final<<<NB, 256>>>(nm, out);
}